// round 11
// baseline (speedup 1.0000x reference)
#include <cuda_runtime.h>
#include <cstdint>

// ---------------- problem sizes (fixed) ----------------
#define B_ROWS 16384
#define EMB    1024
#define HD     128
#define NJ     11              // Taylor terms j = 0..10
#define K2     (NJ*HD)         // 1408

// ---------------- scratch (device globals; allocation-free) ----------------
__device__ float g_Y[2*B_ROWS*HD];     // [32768,128] projections (even=values, odd=mask)
__device__ float g_CsT[HD*K2];         // [k_out(128)][j*128+h]  (GEMM2 B, K-major)
__device__ float g_sigma[K2];          // sigma[j*128+h] = sum_k c^j/j!

__constant__ float c_invfact[NJ] = {
    1.0f, 1.0f, 0.5f, 1.0f/6.0f, 1.0f/24.0f, 1.0f/120.0f, 1.0f/720.0f,
    1.0f/5040.0f, 1.0f/40320.0f, 1.0f/362880.0f, 1.0f/3628800.0f
};

// ---------------- helpers ----------------
__device__ __forceinline__ uint32_t cvta_sh(const void* p) {
    uint32_t a;
    asm("{ .reg .u64 t; cvta.to.shared.u64 t, %1; cvt.u32.u64 %0, t; }" : "=r"(a) : "l"(p));
    return a;
}
__device__ __forceinline__ void cpasync16(uint32_t d, const void* s)
{
    asm volatile("cp.async.cg.shared.global [%0], [%1], 16;\n" :: "r"(d), "l"(s));
}
__device__ __forceinline__ void cp_commit() { asm volatile("cp.async.commit_group;\n" ::: "memory"); }
template<int N> __device__ __forceinline__ void cp_wait() { asm volatile("cp.async.wait_group %0;\n" :: "n"(N) : "memory"); }

__device__ __forceinline__ void ldm_x4(uint32_t addr, uint32_t* r)
{
    asm volatile("ldmatrix.sync.aligned.m8n8.x4.shared.b16 {%0,%1,%2,%3}, [%4];"
                 : "=r"(r[0]), "=r"(r[1]), "=r"(r[2]), "=r"(r[3]) : "r"(addr));
}
__device__ __forceinline__ void mma_tf32(float* c, const uint32_t* a, uint32_t b0, uint32_t b1)
{
    asm volatile(
        "mma.sync.aligned.m16n8k8.row.col.f32.tf32.tf32.f32 "
        "{%0,%1,%2,%3},{%4,%5,%6,%7},{%8,%9},{%0,%1,%2,%3};\n"
        : "+f"(c[0]), "+f"(c[1]), "+f"(c[2]), "+f"(c[3])
        : "r"(a[0]), "r"(a[1]), "r"(a[2]), "r"(a[3]), "r"(b0), "r"(b1));
}

// ---------------- prologue: CsT (coalesced) + sigma (shfl reduce) ----------------
__global__ void k_prep(const float* __restrict__ cov)
{
    const int bid = blockIdx.x, tid = threadIdx.x;
    if (bid < 128) {
        const int k = bid, h = tid;
        float c = cov[h*HD + k];
        float p = 1.0f;
        #pragma unroll
        for (int j = 0; j < NJ; j++) {
            g_CsT[(size_t)k*K2 + j*HD + h] = p * c_invfact[j];
            p *= c;
        }
    } else {
        const int h = bid - 128, k = tid;
        __shared__ float s_part[4];
        float c = cov[h*HD + k];
        float p = 1.0f;
        #pragma unroll
        for (int j = 0; j < NJ; j++) {
            float v = p * c_invfact[j];
            #pragma unroll
            for (int s = 16; s > 0; s >>= 1) v += __shfl_xor_sync(0xffffffffu, v, s);
            if ((k & 31) == 0) s_part[k >> 5] = v;
            __syncthreads();
            if (k == 0) g_sigma[j*HD + h] = s_part[0] + s_part[1] + s_part[2] + s_part[3];
            __syncthreads();
            p *= c;
        }
    }
}

// =====================================================================
// GEMM1 (tf32): g_Y[32768,128] = x[32768,1024] @ W[128,1024]^T
// Block 128x128, BK=32, 128 thr = 4 warps (2M x 2N), warp tile 64x64.
// 3-stage cp.async; ONE barrier per chunk; ldmatrix feed (8 LDSM : 32 MMA).
// =====================================================================
#define TILE_F 4608            // 128*36 floats per stage buffer (18432 B)
#define G1_SMEM (6*TILE_F*4)   // 3 stages A + 3 stages B = 110592 B

__global__ void __launch_bounds__(128, 2)
k_gemm(const float* __restrict__ A, const float* __restrict__ Bm)
{
    extern __shared__ __align__(16) float sm[];
    const uint32_t AsA = cvta_sh(sm);                  // 3 stages
    const uint32_t BsA = AsA + 3*TILE_F*4;             // 3 stages

    const int tid = threadIdx.x, lane = tid & 31, warp = tid >> 5;
    const int wm = warp & 1, wn = warp >> 1;           // 2 x 2 warp grid
    const int mBase = blockIdx.x * 128;

    auto load = [&](int c) {
        const int st = c % 3, k0 = c * 32;
        #pragma unroll
        for (int i = 0; i < 8; i++) {
            int idx = tid + i * 128, r = idx >> 3, kv = (idx & 7) * 4;
            uint32_t off = (uint32_t)((st*TILE_F + r*36 + kv) << 2);
            cpasync16(AsA + off, A  + (size_t)(mBase + r) * EMB + k0 + kv);
            cpasync16(BsA + off, Bm + (size_t)r * EMB + k0 + kv);
        }
        cp_commit();
    };

    float acc[4][8][4] = {};

    const uint32_t rSel = lane & 15;
    const uint32_t cSel = ((lane >> 4) & 1) * 4;
    uint32_t aOff[4], bOff[4];
    #pragma unroll
    for (int t = 0; t < 4; t++) {
        aOff[t] = ((wm*64 + t*16 + rSel)*36 + cSel) * 4;
        bOff[t] = ((wn*64 + t*16 + rSel)*36 + cSel) * 4;
    }

    const int nCh = EMB / 32;   // 32
    load(0); load(1);
    cp_wait<1>();
    __syncthreads();

    for (int c = 0; c < nCh; c++) {
        if (c + 2 < nCh) load(c + 2); else cp_commit();

        const uint32_t aB = AsA + (uint32_t)(((c % 3) * TILE_F) << 2);
        const uint32_t bB = BsA + (uint32_t)(((c % 3) * TILE_F) << 2);
        #pragma unroll
        for (int ks = 0; ks < 4; ks++) {
            uint32_t aq[4][4], bq[4][4];
            #pragma unroll
            for (int t = 0; t < 4; t++) ldm_x4(aB + aOff[t] + ks*32, aq[t]);
            #pragma unroll
            for (int t = 0; t < 4; t++) ldm_x4(bB + bOff[t] + ks*32, bq[t]);
            #pragma unroll
            for (int mt = 0; mt < 4; mt++)
                #pragma unroll
                for (int nt = 0; nt < 8; nt++)
                    mma_tf32(acc[mt][nt], aq[mt],
                             bq[nt >> 1][nt & 1], bq[nt >> 1][2 + (nt & 1)]);
        }
        cp_wait<1>();
        __syncthreads();
    }

    // epilogue -> g_Y
    const int g = lane >> 2, tg = lane & 3;
    #pragma unroll
    for (int mt = 0; mt < 4; mt++) {
        const size_t r0 = (size_t)(mBase + wm*64 + mt*16 + g);
        #pragma unroll
        for (int nt = 0; nt < 8; nt++) {
            const int c0 = wn*64 + nt*8 + tg*2;
            *(float2*)(g_Y + r0       * HD + c0) = make_float2(acc[mt][nt][0], acc[mt][nt][1]);
            *(float2*)(g_Y + (r0 + 8) * HD + c0) = make_float2(acc[mt][nt][2], acc[mt][nt][3]);
        }
    }
}

// =====================================================================
// k_out (tf32): fused (softmax-normalize + GEMM2), 4 warps, 64x64 warp tiles.
// Fragment double-buffering across ks (occ 1: hide LDSM latency under MMA).
// =====================================================================
#define KO_BS_OFF   0                     // 3 x 18432 = 55296
#define KO_M_OFF    55296                 // fp32 [128][132] = 67584
#define KO_CUR_OFF  122880                // fp32 [128][132] = 67584
#define KO_SIG_OFF  190464                // fp32 [1408]     = 5632
#define KO_SMEM     196096

__global__ void __launch_bounds__(128, 1)
k_out(const float* __restrict__ bias, float* __restrict__ out)
{
    extern __shared__ __align__(16) char smc[];
    float* m_s  = (float*)(smc + KO_M_OFF);
    float* curS = (float*)(smc + KO_CUR_OFF);
    float* sigS = (float*)(smc + KO_SIG_OFF);

    const int tid = threadIdx.x, lane = tid & 31, warp = tid >> 5;
    const int wm = warp & 1, wn = warp >> 1;
    const int mBase = blockIdx.x * 128;
    const uint32_t BsA = cvta_sh(smc + KO_BS_OFF);
    const uint32_t curA = cvta_sh(curS);

    auto loadB = [&](int c) {
        const int st = c % 3;
        #pragma unroll
        for (int i = 0; i < 8; i++) {
            int idx = tid + i * 128, r = idx >> 3, kv = (idx & 7) * 4;
            cpasync16(BsA + (uint32_t)((st*TILE_F + r*36 + kv) << 2),
                      g_CsT + (size_t)r * K2 + c*32 + kv);
        }
        cp_commit();
    };

    for (int i = tid; i < K2; i += 128) sigS[i] = g_sigma[i];
    loadB(0); loadB(1);
    __syncthreads();                      // sigS fully written before init reads it

    // init: m_s = m, curS = w = v / D   (D = sum_j m^j * sigma[j][h])
    #pragma unroll 4
    for (int it = 0; it < 128; it++) {
        const int e = tid + it * 128;
        const int r = e >> 7, h = e & 127;
        const float v = g_Y[(size_t)(2*(mBase + r)    ) * HD + h];
        const float m = g_Y[(size_t)(2*(mBase + r) + 1) * HD + h];
        float p = 1.0f, D = 0.0f;
        #pragma unroll
        for (int j = 0; j < NJ; j++) { D = fmaf(p, sigS[j*HD + h], D); p *= m; }
        m_s [r*132 + h] = m;
        curS[r*132 + h] = v / D;
    }
    cp_wait<1>();
    __syncthreads();

    float acc[4][8][4] = {};

    const uint32_t rSel = lane & 15;
    const uint32_t cSel = ((lane >> 4) & 1) * 4;
    uint32_t aOff[4], bOff[4];
    #pragma unroll
    for (int t = 0; t < 4; t++) {
        aOff[t] = ((wm*64 + t*16 + rSel)*132 + cSel) * 4;   // cur stride 132 floats
        bOff[t] = ((wn*64 + t*16 + rSel)*36 + cSel) * 4;
    }

    const int nCh = K2 / 32;   // 44
    for (int c = 0; c < nCh; c++) {
        if (c + 2 < nCh) loadB(c + 2); else cp_commit();

        const uint32_t aB = curA + (uint32_t)((c & 3) * 128);   // +32 floats per h-block
        const uint32_t bB = BsA + (uint32_t)(((c % 3) * TILE_F) << 2);

        uint32_t aq[2][4][4], bq[2][4][4];
        #pragma unroll
        for (int t = 0; t < 4; t++) { ldm_x4(aB + aOff[t], aq[0][t]); ldm_x4(bB + bOff[t], bq[0][t]); }
        #pragma unroll
        for (int ks = 0; ks < 4; ks++) {
            const int cur = ks & 1, nxt = cur ^ 1;
            if (ks < 3) {
                #pragma unroll
                for (int t = 0; t < 4; t++) {
                    ldm_x4(aB + aOff[t] + (ks+1)*32, aq[nxt][t]);
                    ldm_x4(bB + bOff[t] + (ks+1)*32, bq[nxt][t]);
                }
            }
            #pragma unroll
            for (int mt = 0; mt < 4; mt++)
                #pragma unroll
                for (int nt = 0; nt < 8; nt++)
                    mma_tf32(acc[mt][nt], aq[cur][mt],
                             bq[cur][nt >> 1][nt & 1], bq[cur][nt >> 1][2 + (nt & 1)]);
        }
        cp_wait<1>();
        __syncthreads();

        if ((c & 3) == 3 && c < nCh - 1) {          // j boundary: cur *= m
            float4* cu = (float4*)curS;
            float4* mv = (float4*)m_s;
            #pragma unroll 4
            for (int it = 0; it < 32; it++) {
                const int e = tid + it * 128;       // 0..4095 data float4 slots
                const int r = e >> 5, s = e & 31;   // 32 data-float4 per row, stride 33
                const int off = r*33 + s;
                float4 a = cu[off];
                const float4 b = mv[off];
                a.x *= b.x; a.y *= b.y; a.z *= b.z; a.w *= b.w;
                cu[off] = a;
            }
            __syncthreads();
        }
    }

    // epilogue: + bias -> out
    const int g = lane >> 2, tg = lane & 3;
    #pragma unroll
    for (int mt = 0; mt < 4; mt++) {
        const size_t r0 = (size_t)(mBase + wm*64 + mt*16 + g);
        #pragma unroll
        for (int nt = 0; nt < 8; nt++) {
            const int c0 = wn*64 + nt*8 + tg*2;
            const float b0 = bias[c0], b1 = bias[c0 + 1];
            *(float2*)(out + r0       * HD + c0) = make_float2(acc[mt][nt][0] + b0, acc[mt][nt][1] + b1);
            *(float2*)(out + (r0 + 8) * HD + c0) = make_float2(acc[mt][nt][2] + b0, acc[mt][nt][3] + b1);
        }
    }
}

// ---------------- launch ----------------
extern "C" void kernel_launch(void* const* d_in, const int* in_sizes, int n_in,
                              void* d_out, int out_size)
{
    const float* x    = (const float*)d_in[0];   // [16384,2,1024]
    const float* W    = (const float*)d_in[1];   // [128,1024]
    const float* cov  = (const float*)d_in[2];   // [128,128]
    const float* bias = (const float*)d_in[3];   // [128]
    float* out = (float*)d_out;                  // [16384,128]

    cudaFuncSetAttribute(k_gemm, cudaFuncAttributeMaxDynamicSharedMemorySize, G1_SMEM);
    cudaFuncSetAttribute(k_out,  cudaFuncAttributeMaxDynamicSharedMemorySize, KO_SMEM);

    k_prep<<<256, 128>>>(cov);
    k_gemm<<<2*B_ROWS/128, 128, G1_SMEM>>>(x, W);
    k_out<<<B_ROWS/128, 128, KO_SMEM>>>(bias, out);
}

// round 12
// speedup vs baseline: 1.8866x; 1.8866x over previous
#include <cuda_runtime.h>
#include <cstdint>

// ---------------- problem sizes (fixed) ----------------
#define B_ROWS 16384
#define EMB    1024
#define HD     128
#define NJ     11              // Taylor terms j = 0..10
#define K2     (NJ*HD)         // 1408

// ---------------- scratch (device globals; allocation-free) ----------------
__device__ float g_Y[2*B_ROWS*HD];     // [32768,128] projections (even=values, odd=mask)
__device__ float g_CsT[HD*K2];         // [k_out(128)][j*128+h]  (GEMM2 B, K-major)
__device__ float g_sigma[K2];          // sigma[j*128+h] = sum_k c^j/j!

__constant__ float c_invfact[NJ] = {
    1.0f, 1.0f, 0.5f, 1.0f/6.0f, 1.0f/24.0f, 1.0f/120.0f, 1.0f/720.0f,
    1.0f/5040.0f, 1.0f/40320.0f, 1.0f/362880.0f, 1.0f/3628800.0f
};

// ---------------- helpers ----------------
__device__ __forceinline__ uint32_t cvta_sh(const void* p) {
    uint32_t a;
    asm("{ .reg .u64 t; cvta.to.shared.u64 t, %1; cvt.u32.u64 %0, t; }" : "=r"(a) : "l"(p));
    return a;
}
__device__ __forceinline__ void cpasync16(uint32_t d, const void* s)
{
    asm volatile("cp.async.cg.shared.global [%0], [%1], 16;\n" :: "r"(d), "l"(s));
}
__device__ __forceinline__ void cp_commit() { asm volatile("cp.async.commit_group;\n" ::: "memory"); }
template<int N> __device__ __forceinline__ void cp_wait() { asm volatile("cp.async.wait_group %0;\n" :: "n"(N) : "memory"); }

__device__ __forceinline__ void ldm_x4(uint32_t addr, uint32_t* r)
{
    asm volatile("ldmatrix.sync.aligned.m8n8.x4.shared.b16 {%0,%1,%2,%3}, [%4];"
                 : "=r"(r[0]), "=r"(r[1]), "=r"(r[2]), "=r"(r[3]) : "r"(addr));
}
__device__ __forceinline__ void mma_tf32(float* c, const uint32_t* a, uint32_t b0, uint32_t b1)
{
    asm volatile(
        "mma.sync.aligned.m16n8k8.row.col.f32.tf32.tf32.f32 "
        "{%0,%1,%2,%3},{%4,%5,%6,%7},{%8,%9},{%0,%1,%2,%3};\n"
        : "+f"(c[0]), "+f"(c[1]), "+f"(c[2]), "+f"(c[3])
        : "r"(a[0]), "r"(a[1]), "r"(a[2]), "r"(a[3]), "r"(b0), "r"(b1));
}

// =====================================================================
// GEMM1 (tf32) + folded prologue.
// Blocks 0..255:   g_Y[32768,128] = x @ W^T  (128x128 tile, 8 warps 4Mx2N,
//                  warp 32x64, BK=32, 3-stage cp.async, 1 barrier/chunk)
// Blocks 256..383: g_CsT[k][j*128+h] = cov[h][k]^j/j!   (coalesced)
// Blocks 384..511: g_sigma[j*128+h] = sum_k cov[h][k]^j/j!  (shfl, 1 barrier)
// =====================================================================
#define TILE_F 4608            // 128*36 floats per stage buffer (18432 B)
#define G1_SMEM (6*TILE_F*4)   // 3 stages A + 3 stages B = 110592 B

__global__ void __launch_bounds__(256, 2)
k_gemm(const float* __restrict__ A, const float* __restrict__ Bm,
       const float* __restrict__ cov)
{
    const int tid = threadIdx.x;

    if (blockIdx.x >= 256) {                   // ---- folded prologue blocks ----
        const int pb = blockIdx.x - 256;
        if (pb < 128) {
            if (tid < 128) {
                const int k = pb, h = tid;
                float c = cov[h*HD + k];
                float p = 1.0f;
                #pragma unroll
                for (int j = 0; j < NJ; j++) {
                    g_CsT[(size_t)k*K2 + j*HD + h] = p * c_invfact[j];
                    p *= c;
                }
            }
        } else {
            const int h = pb - 128;
            __shared__ float part[4][NJ];
            if (tid < 128) {
                const int k = tid;
                float c = cov[h*HD + k];
                float p = 1.0f;
                #pragma unroll
                for (int j = 0; j < NJ; j++) {
                    float v = p * c_invfact[j];
                    #pragma unroll
                    for (int s = 16; s > 0; s >>= 1) v += __shfl_xor_sync(0xffffffffu, v, s);
                    if ((k & 31) == 0) part[k >> 5][j] = v;
                    p *= c;
                }
            }
            __syncthreads();
            if (tid < NJ)
                g_sigma[tid*HD + h] = part[0][tid] + part[1][tid] + part[2][tid] + part[3][tid];
        }
        return;
    }

    // ---- GEMM blocks ----
    extern __shared__ __align__(16) float sm[];
    const uint32_t AsA = cvta_sh(sm);                  // 3 stages
    const uint32_t BsA = AsA + 3*TILE_F*4;             // 3 stages

    const int lane = tid & 31, warp = tid >> 5;
    const int wm = warp & 3, wn = warp >> 2;
    const int mBase = blockIdx.x * 128;

    auto load = [&](int c) {
        const int st = c % 3, k0 = c * 32;
        #pragma unroll
        for (int i = 0; i < 4; i++) {
            int idx = tid + i * 256, r = idx >> 3, kv = (idx & 7) * 4;
            uint32_t off = (uint32_t)((st*TILE_F + r*36 + kv) << 2);
            cpasync16(AsA + off, A  + (size_t)(mBase + r) * EMB + k0 + kv);
            cpasync16(BsA + off, Bm + (size_t)r * EMB + k0 + kv);
        }
        cp_commit();
    };

    float acc[2][8][4] = {};

    const uint32_t rSel = lane & 15;
    const uint32_t cSel = ((lane >> 4) & 1) * 4;
    const uint32_t aOff0 = ((wm*32 + rSel)*36 + cSel) * 4;
    const uint32_t aOff1 = aOff0 + 16*36*4;
    uint32_t bOff[4];
    #pragma unroll
    for (int p = 0; p < 4; p++) bOff[p] = ((wn*64 + p*16 + rSel)*36 + cSel) * 4;

    const int nCh = EMB / 32;   // 32
    load(0); load(1);
    cp_wait<1>();
    __syncthreads();

    for (int c = 0; c < nCh; c++) {
        if (c + 2 < nCh) load(c + 2); else cp_commit();

        const uint32_t aB = AsA + (uint32_t)(((c % 3) * TILE_F) << 2);
        const uint32_t bB = BsA + (uint32_t)(((c % 3) * TILE_F) << 2);
        #pragma unroll
        for (int ks = 0; ks < 4; ks++) {
            uint32_t a0[4], a1[4], bq[4][4];
            ldm_x4(aB + aOff0 + ks*32, a0);
            ldm_x4(aB + aOff1 + ks*32, a1);
            #pragma unroll
            for (int p = 0; p < 4; p++) ldm_x4(bB + bOff[p] + ks*32, bq[p]);
            #pragma unroll
            for (int nt = 0; nt < 8; nt++) {
                const uint32_t b0 = bq[nt >> 1][nt & 1];
                const uint32_t b1 = bq[nt >> 1][2 + (nt & 1)];
                mma_tf32(acc[0][nt], a0, b0, b1);
                mma_tf32(acc[1][nt], a1, b0, b1);
            }
        }
        cp_wait<1>();
        __syncthreads();
    }

    // epilogue -> g_Y
    const int g = lane >> 2, tg = lane & 3;
    #pragma unroll
    for (int mt = 0; mt < 2; mt++) {
        const size_t r0 = (size_t)(mBase + wm*32 + mt*16 + g);
        #pragma unroll
        for (int nt = 0; nt < 8; nt++) {
            const int c0 = wn*64 + nt*8 + tg*2;
            *(float2*)(g_Y + r0       * HD + c0) = make_float2(acc[mt][nt][0], acc[mt][nt][1]);
            *(float2*)(g_Y + (r0 + 8) * HD + c0) = make_float2(acc[mt][nt][2], acc[mt][nt][3]);
        }
    }
}

// =====================================================================
// k_out (tf32): fused (softmax-normalize + GEMM2), 64-row tiles, occ 2.
// 256 thr = 8 warps (2M x 4N), warp tile 32x32; 2-stage B; grid 256.
// 16 warps/SM for latency hiding. smem 110080 B (2 CTAs/SM).
// =====================================================================
#define KO_BS_OFF   0                     // 2 x 18432 = 36864
#define KO_M_OFF    36864                 // fp32 [64][132] = 33792
#define KO_CUR_OFF  70656                 // fp32 [64][132] = 33792
#define KO_SIG_OFF  104448                // fp32 [1408]    = 5632
#define KO_SMEM     110080

__global__ void __launch_bounds__(256, 2)
k_out(const float* __restrict__ bias, float* __restrict__ out)
{
    extern __shared__ __align__(16) char smc[];
    float* m_s  = (float*)(smc + KO_M_OFF);
    float* curS = (float*)(smc + KO_CUR_OFF);
    float* sigS = (float*)(smc + KO_SIG_OFF);

    const int tid = threadIdx.x, lane = tid & 31, warp = tid >> 5;
    const int wm = warp & 1, wn = warp >> 1;          // 2M x 4N
    const int mBase = blockIdx.x * 64;
    const uint32_t BsA = cvta_sh(smc + KO_BS_OFF);
    const uint32_t curA = cvta_sh(curS);

    auto loadB = [&](int c) {
        const int st = c & 1;
        #pragma unroll
        for (int i = 0; i < 4; i++) {
            int idx = tid + i * 256, r = idx >> 3, kv = (idx & 7) * 4;
            cpasync16(BsA + (uint32_t)((st*TILE_F + r*36 + kv) << 2),
                      g_CsT + (size_t)r * K2 + c*32 + kv);
        }
        cp_commit();
    };

    loadB(0);
    for (int i = tid; i < K2; i += 256) sigS[i] = g_sigma[i];
    __syncthreads();                      // sigS fully written before init reads it

    // init: m_s = m, curS = w = v / D   (D = sum_j m^j * sigma[j][h])
    #pragma unroll 4
    for (int it = 0; it < 32; it++) {
        const int e = tid + it * 256;
        const int r = e >> 7, h = e & 127;
        const float v = g_Y[(size_t)(2*(mBase + r)    ) * HD + h];
        const float m = g_Y[(size_t)(2*(mBase + r) + 1) * HD + h];
        float p = 1.0f, D = 0.0f;
        #pragma unroll
        for (int j = 0; j < NJ; j++) { D = fmaf(p, sigS[j*HD + h], D); p *= m; }
        m_s [r*132 + h] = m;
        curS[r*132 + h] = v / D;
    }
    cp_wait<0>();
    __syncthreads();

    float acc[2][4][4] = {};

    const uint32_t rSel = lane & 15;
    const uint32_t cSel = ((lane >> 4) & 1) * 4;
    uint32_t aOff[2], bOff[2];
    #pragma unroll
    for (int t = 0; t < 2; t++) {
        aOff[t] = ((wm*32 + t*16 + rSel)*132 + cSel) * 4;   // cur stride 132 floats
        bOff[t] = ((wn*32 + t*16 + rSel)*36 + cSel) * 4;
    }

    const int nCh = K2 / 32;   // 44
    for (int c = 0; c < nCh; c++) {
        if (c + 1 < nCh) loadB(c + 1);

        const uint32_t aB = curA + (uint32_t)((c & 3) * 128);   // +32 floats per h-block
        const uint32_t bB = BsA + (uint32_t)(((c & 1) * TILE_F) << 2);
        #pragma unroll
        for (int ks = 0; ks < 4; ks++) {
            uint32_t aq[2][4], bq[2][4];
            #pragma unroll
            for (int t = 0; t < 2; t++) {
                ldm_x4(aB + aOff[t] + ks*32, aq[t]);
                ldm_x4(bB + bOff[t] + ks*32, bq[t]);
            }
            #pragma unroll
            for (int mt = 0; mt < 2; mt++)
                #pragma unroll
                for (int nt = 0; nt < 4; nt++)
                    mma_tf32(acc[mt][nt], aq[mt],
                             bq[nt >> 1][nt & 1], bq[nt >> 1][2 + (nt & 1)]);
        }
        cp_wait<0>();
        __syncthreads();

        if ((c & 3) == 3 && c < nCh - 1) {          // j boundary: cur *= m
            float4* cu = (float4*)curS;
            float4* mv = (float4*)m_s;
            #pragma unroll 4
            for (int it = 0; it < 8; it++) {
                const int e = tid + it * 256;       // 0..2047 data float4 slots
                const int r = e >> 5, s = e & 31;   // 32 data-float4 per row, stride 33
                const int off = r*33 + s;
                float4 a = cu[off];
                const float4 b = mv[off];
                a.x *= b.x; a.y *= b.y; a.z *= b.z; a.w *= b.w;
                cu[off] = a;
            }
            __syncthreads();
        }
    }

    // epilogue: + bias -> out
    const int g = lane >> 2, tg = lane & 3;
    #pragma unroll
    for (int mt = 0; mt < 2; mt++) {
        const size_t r0 = (size_t)(mBase + wm*32 + mt*16 + g);
        #pragma unroll
        for (int nt = 0; nt < 4; nt++) {
            const int c0 = wn*32 + nt*8 + tg*2;
            const float b0 = bias[c0], b1 = bias[c0 + 1];
            *(float2*)(out + r0       * HD + c0) = make_float2(acc[mt][nt][0] + b0, acc[mt][nt][1] + b1);
            *(float2*)(out + (r0 + 8) * HD + c0) = make_float2(acc[mt][nt][2] + b0, acc[mt][nt][3] + b1);
        }
    }
}

// ---------------- launch ----------------
extern "C" void kernel_launch(void* const* d_in, const int* in_sizes, int n_in,
                              void* d_out, int out_size)
{
    const float* x    = (const float*)d_in[0];   // [16384,2,1024]
    const float* W    = (const float*)d_in[1];   // [128,1024]
    const float* cov  = (const float*)d_in[2];   // [128,128]
    const float* bias = (const float*)d_in[3];   // [128]
    float* out = (float*)d_out;                  // [16384,128]

    cudaFuncSetAttribute(k_gemm, cudaFuncAttributeMaxDynamicSharedMemorySize, G1_SMEM);
    cudaFuncSetAttribute(k_out,  cudaFuncAttributeMaxDynamicSharedMemorySize, KO_SMEM);

    k_gemm<<<512, 256, G1_SMEM>>>(x, W, cov);    // blocks 256..511 do the prologue
    k_out<<<256, 256, KO_SMEM>>>(bias, out);
}

// round 13
// speedup vs baseline: 2.6675x; 1.4139x over previous
#include <cuda_runtime.h>
#include <cuda_fp16.h>
#include <cstdint>

// ---------------- problem sizes (fixed) ----------------
#define B_ROWS 16384
#define EMB    1024
#define HD     128
#define NJ     11              // Taylor terms j = 0..10
#define K2     (NJ*HD)         // 1408

// ---------------- scratch (device globals; allocation-free) ----------------
__device__ float  g_Y[2*B_ROWS*HD];   // [32768,128] projections (even=values, odd=mask)
__device__ __half g_Wh[HD*EMB];       // W in fp16, [128][1024]
__device__ __half g_CsH[HD*K2];       // [k_out(128)][j*128+h] = fp16(cov[h][k]^j)  (no 1/j!)
__device__ float  g_sigma[K2];        // sigma'[j*128+h] = sum_k c^j  (no 1/j!)

__constant__ float c_rj[12] = { 0.0f, 1.0f, 0.5f, 1.0f/3.0f, 0.25f, 0.2f, 1.0f/6.0f,
                                1.0f/7.0f, 0.125f, 1.0f/9.0f, 0.1f, 1.0f/11.0f };

// ---------------- helpers ----------------
__device__ __forceinline__ uint32_t cvta_sh(const void* p) {
    uint32_t a;
    asm("{ .reg .u64 t; cvta.to.shared.u64 t, %1; cvt.u32.u64 %0, t; }" : "=r"(a) : "l"(p));
    return a;
}
__device__ __forceinline__ void cpasync16(uint32_t d, const void* s)
{
    asm volatile("cp.async.cg.shared.global [%0], [%1], 16;\n" :: "r"(d), "l"(s));
}
__device__ __forceinline__ void cp_commit() { asm volatile("cp.async.commit_group;\n" ::: "memory"); }
template<int N> __device__ __forceinline__ void cp_wait() { asm volatile("cp.async.wait_group %0;\n" :: "n"(N) : "memory"); }

__device__ __forceinline__ void ldm_x4(uint32_t addr, uint32_t* r)
{
    asm volatile("ldmatrix.sync.aligned.m8n8.x4.shared.b16 {%0,%1,%2,%3}, [%4];"
                 : "=r"(r[0]), "=r"(r[1]), "=r"(r[2]), "=r"(r[3]) : "r"(addr));
}
__device__ __forceinline__ void mma_f16(float* c, const uint32_t* a, uint32_t b0, uint32_t b1)
{
    asm volatile(
        "mma.sync.aligned.m16n8k16.row.col.f32.f16.f16.f32 "
        "{%0,%1,%2,%3},{%4,%5,%6,%7},{%8,%9},{%0,%1,%2,%3};\n"
        : "+f"(c[0]), "+f"(c[1]), "+f"(c[2]), "+f"(c[3])
        : "r"(a[0]), "r"(a[1]), "r"(a[2]), "r"(a[3]), "r"(b0), "r"(b1));
}
__device__ __forceinline__ uint32_t pack_h2(float lo, float hi)
{
    __half2 h = __floats2half2_rn(lo, hi);   // x=lo, y=hi
    return *(uint32_t*)&h;
}

// ---------------- k_w: W fp32 -> fp16 (one-off, ~1.5us) ----------------
__global__ void k_w(const float* __restrict__ W)
{
    const int u = blockIdx.x * 256 + threadIdx.x;     // float4 slot 0..32767
    float4 f = *(const float4*)(W + (size_t)u * 4);
    uint2 o;
    o.x = pack_h2(f.x, f.y);
    o.y = pack_h2(f.z, f.w);
    *(uint2*)(g_Wh + (size_t)u * 4) = o;
}

// =====================================================================
// k_gemm (fp16) + folded prologue.
// Blocks 0..255:   g_Y[32768,128] = x @ W^T. 128x128 tile, 8 warps 4Mx2N
//                  (warp 32x64), BK=32; A: LDG fp32->cvt->STS (2-stage);
//                  B: cp.async fp16 (3-stage); ONE barrier per chunk.
// Blocks 256..383: g_CsH[k][j*128+h] = fp16(cov[h][k]^j)
// Blocks 384..511: g_sigma'[j*128+h] = sum_k cov[h][k]^j
// =====================================================================
#define G1_ST   40                 // halves per smem row (32 + 8 pad)
#define G1_TILE (128*G1_ST*2)      // 10240 B per stage
#define G1_SMEM (5*G1_TILE)        // A x2 + B x3 = 51200 B

__global__ void __launch_bounds__(256, 2)
k_gemm(const float* __restrict__ A, const float* __restrict__ cov)
{
    const int tid = threadIdx.x;

    if (blockIdx.x >= 256) {                   // ---- folded prologue ----
        const int pb = blockIdx.x - 256;
        if (pb < 128) {
            if (tid < 128) {
                const int k = pb, h = tid;
                float c = cov[h*HD + k];
                float p = 1.0f;
                #pragma unroll
                for (int j = 0; j < NJ; j++) {
                    g_CsH[(size_t)k*K2 + j*HD + h] = __float2half(p);
                    p *= c;
                }
            }
        } else {
            const int h = pb - 128;
            __shared__ float part[4][NJ];
            if (tid < 128) {
                const int k = tid;
                float c = cov[h*HD + k];
                float p = 1.0f;
                #pragma unroll
                for (int j = 0; j < NJ; j++) {
                    float v = p;
                    #pragma unroll
                    for (int s = 16; s > 0; s >>= 1) v += __shfl_xor_sync(0xffffffffu, v, s);
                    if ((k & 31) == 0) part[k >> 5][j] = v;
                    p *= c;
                }
            }
            __syncthreads();
            if (tid < NJ)
                g_sigma[tid*HD + h] = part[0][tid] + part[1][tid] + part[2][tid] + part[3][tid];
        }
        return;
    }

    // ---- GEMM blocks ----
    extern __shared__ __align__(16) char smem[];
    const uint32_t AsA = cvta_sh(smem);               // 2 stages
    const uint32_t BsA = AsA + 2*G1_TILE;             // 3 stages

    const int lane = tid & 31, warp = tid >> 5;
    const int wm = warp & 3, wn = warp >> 2;
    const int mBase = blockIdx.x * 128;

    // A staging: 4 float4/thread/chunk; slot s = tid + i*256: r = ar+i*32, q = aq
    const int ar = tid >> 3, aq = tid & 7;
    float4 a_st[4];

    auto ldA = [&](int c) {
        const int k0 = c * 32;
        #pragma unroll
        for (int i = 0; i < 4; i++)
            a_st[i] = *(const float4*)(A + (size_t)(mBase + ar + i*32) * EMB + k0 + aq*4);
    };
    auto stA = [&](int c) {
        const uint32_t base = AsA + (uint32_t)((c & 1) * G1_TILE);
        #pragma unroll
        for (int i = 0; i < 4; i++) {
            uint2 o;
            o.x = pack_h2(a_st[i].x, a_st[i].y);
            o.y = pack_h2(a_st[i].z, a_st[i].w);
            asm volatile("st.shared.v2.b32 [%0], {%1, %2};" ::
                "r"(base + (uint32_t)(((ar + i*32)*G1_ST + aq*4) * 2)), "r"(o.x), "r"(o.y));
        }
    };
    // B: 2 cp.async/thread/chunk (128 rows x 64B): slot s = tid + i*256: r = s>>2, q = s&3
    const int br = tid >> 2, bq_ = tid & 3;
    auto ldB = [&](int c) {
        const int k0 = c * 32, st = c % 3;
        #pragma unroll
        for (int i = 0; i < 2; i++)
            cpasync16(BsA + (uint32_t)(st*G1_TILE + ((br + i*64)*G1_ST + bq_*8)*2),
                      g_Wh + (size_t)(br + i*64) * EMB + k0 + bq_*8);
        cp_commit();
    };

    float acc[2][8][4] = {};

    const uint32_t rSel = lane & 15;
    const uint32_t hSel = (lane >> 4) * 8;            // halves
    const uint32_t aOff0 = ((wm*32 + rSel)*G1_ST + hSel) * 2;
    const uint32_t aOff1 = aOff0 + 16*G1_ST*2;
    uint32_t bOff[4];
    #pragma unroll
    for (int p = 0; p < 4; p++) bOff[p] = ((wn*64 + p*16 + rSel)*G1_ST + hSel) * 2;

    const int nCh = EMB / 32;   // 32
    ldA(0); stA(0); ldB(0);
    ldA(1); ldB(1);
    cp_wait<1>();
    __syncthreads();

    for (int c = 0; c < nCh; c++) {
        if (c + 2 < nCh) ldB(c + 2); else cp_commit();
        if (c + 1 < nCh) stA(c + 1);
        if (c + 2 < nCh) ldA(c + 2);

        const uint32_t aB = AsA + (uint32_t)((c & 1) * G1_TILE);
        const uint32_t bB = BsA + (uint32_t)((c % 3) * G1_TILE);
        #pragma unroll
        for (int ks = 0; ks < 2; ks++) {              // k16 steps
            uint32_t a0[4], a1[4], bq[4][4];
            ldm_x4(aB + aOff0 + ks*32, a0);
            ldm_x4(aB + aOff1 + ks*32, a1);
            #pragma unroll
            for (int p = 0; p < 4; p++) ldm_x4(bB + bOff[p] + ks*32, bq[p]);
            #pragma unroll
            for (int nt = 0; nt < 8; nt++) {
                const uint32_t b0 = bq[nt >> 1][nt & 1];
                const uint32_t b1 = bq[nt >> 1][2 + (nt & 1)];
                mma_f16(acc[0][nt], a0, b0, b1);
                mma_f16(acc[1][nt], a1, b0, b1);
            }
        }
        cp_wait<1>();
        __syncthreads();
    }

    // epilogue -> g_Y (fp32)
    const int g = lane >> 2, tg = lane & 3;
    #pragma unroll
    for (int mt = 0; mt < 2; mt++) {
        const size_t r0 = (size_t)(mBase + wm*32 + mt*16 + g);
        #pragma unroll
        for (int nt = 0; nt < 8; nt++) {
            const int c0 = wn*64 + nt*8 + tg*2;
            *(float2*)(g_Y + r0       * HD + c0) = make_float2(acc[mt][nt][0], acc[mt][nt][1]);
            *(float2*)(g_Y + (r0 + 8) * HD + c0) = make_float2(acc[mt][nt][2], acc[mt][nt][3]);
        }
    }
}

// =====================================================================
// k_out (fp16): fused (softmax-normalize + GEMM2), 64-row tiles, occ 2.
// cur_j = w * m^j / j!  (fp32 chain; fp16 mirror curH for ldmatrix)
// B_j   = c^j (fp16, precomputed).  out = sum cur_j @ B_j^T + bias.
// 8 warps (2M x 4N), warp 32x32; 2-stage B cp.async; grid 256.
// =====================================================================
#define KO_BST    40                  // halves per B smem row
#define KO_BTILE  (128*KO_BST*2)      // 10240 B
#define KO_BS_OFF   0                 // 2 stages = 20480
#define KO_M_OFF    20480             // fp32 [64][132] = 33792
#define KO_CUR_OFF  54272             // fp32 [64][132] = 33792
#define KO_CURH_OFF 88064             // fp16 [64][136] = 17408
#define KO_SIG_OFF  105472            // fp32 [1408]    = 5632
#define KO_SMEM     111104

__global__ void __launch_bounds__(256, 2)
k_out(const float* __restrict__ bias, float* __restrict__ out)
{
    extern __shared__ __align__(16) char smc[];
    float*  m_s  = (float*)(smc + KO_M_OFF);
    float*  curS = (float*)(smc + KO_CUR_OFF);
    __half* curH = (__half*)(smc + KO_CURH_OFF);
    float*  sigS = (float*)(smc + KO_SIG_OFF);

    const int tid = threadIdx.x, lane = tid & 31, warp = tid >> 5;
    const int wm = warp & 1, wn = warp >> 1;          // 2M x 4N
    const int mBase = blockIdx.x * 64;
    const uint32_t BsA   = cvta_sh(smc + KO_BS_OFF);
    const uint32_t curHA = cvta_sh(curH);

    // B chunk: 128 rows x 32 halves (64B); 2 cp.async/thread
    auto loadB = [&](int c) {
        const int st = c & 1;
        #pragma unroll
        for (int i = 0; i < 2; i++) {
            const int s = tid + i*256, r = s >> 2, q = s & 3;
            cpasync16(BsA + (uint32_t)(st*KO_BTILE + (r*KO_BST + q*8)*2),
                      g_CsH + (size_t)r * K2 + c*32 + q*8);
        }
        cp_commit();
    };

    loadB(0);
    for (int i = tid; i < K2; i += 256) sigS[i] = g_sigma[i];
    __syncthreads();                  // sigS fully written before init reads it

    // init: m_s = m; curS = w = v / D; curH = fp16(w).  D = sum_j (m^j/j!) sigma'_j
    #pragma unroll 4
    for (int it = 0; it < 32; it++) {
        const int e = tid + it * 256;
        const int r = e >> 7, h = e & 127;
        const float v = g_Y[(size_t)(2*(mBase + r)    ) * HD + h];
        const float m = g_Y[(size_t)(2*(mBase + r) + 1) * HD + h];
        float p = 1.0f, D = 0.0f;
        #pragma unroll
        for (int j = 0; j < NJ; j++) { D = fmaf(p, sigS[j*HD + h], D); p = p * m * c_rj[j+1]; }
        const float w = v / D;
        m_s [r*132 + h] = m;
        curS[r*132 + h] = w;
        curH[r*136 + h] = __float2half(w);
    }
    cp_wait<0>();
    __syncthreads();

    float acc[2][4][4] = {};

    const uint32_t rSel = lane & 15;
    const uint32_t hSel = (lane >> 4) * 8;            // halves
    uint32_t aOff[2], bOff[2];
    #pragma unroll
    for (int t = 0; t < 2; t++) {
        aOff[t] = ((wm*32 + t*16 + rSel)*136 + hSel) * 2;   // curH stride 136 halves
        bOff[t] = ((wn*32 + t*16 + rSel)*KO_BST + hSel) * 2;
    }

    const int nCh = K2 / 32;   // 44 (4 chunks per j)
    for (int c = 0; c < nCh; c++) {
        if (c + 1 < nCh) loadB(c + 1);

        const uint32_t aB = curHA + (uint32_t)((c & 3) * 64);   // +32 halves per h-block
        const uint32_t bB = BsA + (uint32_t)((c & 1) * KO_BTILE);
        #pragma unroll
        for (int ks = 0; ks < 2; ks++) {              // k16 steps
            uint32_t aq2[2][4], bq2[2][4];
            #pragma unroll
            for (int t = 0; t < 2; t++) {
                ldm_x4(aB + aOff[t] + ks*32, aq2[t]);
                ldm_x4(bB + bOff[t] + ks*32, bq2[t]);
            }
            #pragma unroll
            for (int mt = 0; mt < 2; mt++)
                #pragma unroll
                for (int nt = 0; nt < 4; nt++)
                    mma_f16(acc[mt][nt], aq2[mt],
                            bq2[nt >> 1][nt & 1], bq2[nt >> 1][2 + (nt & 1)]);
        }
        cp_wait<0>();
        __syncthreads();

        if ((c & 3) == 3 && c < nCh - 1) {            // j -> j+1: cur *= m/(j+1)
            const float sc = c_rj[(c >> 2) + 1];
            float4* cu = (float4*)curS;
            float4* mv = (float4*)m_s;
            #pragma unroll
            for (int it = 0; it < 8; it++) {
                const int e = tid + it * 256;         // 2048 data float4 slots
                const int r = e >> 5, s4 = e & 31;
                const int off = r*33 + s4;            // float4 stride 33 (=132 floats)
                float4 a = cu[off];
                const float4 b = mv[off];
                a.x *= b.x * sc; a.y *= b.y * sc; a.z *= b.z * sc; a.w *= b.w * sc;
                cu[off] = a;
                uint2 o;
                o.x = pack_h2(a.x, a.y);
                o.y = pack_h2(a.z, a.w);
                *(uint2*)(curH + r*136 + s4*4) = o;
            }
            __syncthreads();
        }
    }

    // epilogue: + bias -> out
    const int g = lane >> 2, tg = lane & 3;
    #pragma unroll
    for (int mt = 0; mt < 2; mt++) {
        const size_t r0 = (size_t)(mBase + wm*32 + mt*16 + g);
        #pragma unroll
        for (int nt = 0; nt < 4; nt++) {
            const int c0 = wn*32 + nt*8 + tg*2;
            const float b0 = bias[c0], b1 = bias[c0 + 1];
            *(float2*)(out + r0       * HD + c0) = make_float2(acc[mt][nt][0] + b0, acc[mt][nt][1] + b1);
            *(float2*)(out + (r0 + 8) * HD + c0) = make_float2(acc[mt][nt][2] + b0, acc[mt][nt][3] + b1);
        }
    }
}

// ---------------- launch ----------------
extern "C" void kernel_launch(void* const* d_in, const int* in_sizes, int n_in,
                              void* d_out, int out_size)
{
    const float* x    = (const float*)d_in[0];   // [16384,2,1024]
    const float* W    = (const float*)d_in[1];   // [128,1024]
    const float* cov  = (const float*)d_in[2];   // [128,128]
    const float* bias = (const float*)d_in[3];   // [128]
    float* out = (float*)d_out;                  // [16384,128]

    cudaFuncSetAttribute(k_gemm, cudaFuncAttributeMaxDynamicSharedMemorySize, G1_SMEM);
    cudaFuncSetAttribute(k_out,  cudaFuncAttributeMaxDynamicSharedMemorySize, KO_SMEM);

    k_w<<<128, 256>>>(W);                        // W -> fp16 (read by k_gemm next launch)
    k_gemm<<<512, 256, G1_SMEM>>>(x, cov);       // blocks 256..511: CsH + sigma'
    k_out<<<256, 256, KO_SMEM>>>(bias, out);
}

// round 14
// speedup vs baseline: 2.7241x; 1.0212x over previous
#include <cuda_runtime.h>
#include <cuda_fp16.h>
#include <cstdint>

// ---------------- problem sizes (fixed) ----------------
#define B_ROWS 16384
#define EMB    1024
#define HD     128
#define NJ     11              // Taylor terms j = 0..10
#define K2     (NJ*HD)         // 1408

// ---------------- scratch (device globals; allocation-free) ----------------
__device__ float  g_Y[2*B_ROWS*HD];   // [32768,128] projections (even=values, odd=mask)
__device__ __half g_Wh[HD*EMB];       // W in fp16, [128][1024]
__device__ __half g_CsH[HD*K2];       // [k_out(128)][j*128+h] = fp16(cov[h][k]^j)  (no 1/j!)
__device__ float  g_sigma[K2];        // sigma'[j*128+h] = sum_k c^j  (no 1/j!)

__constant__ float c_rj[12] = { 0.0f, 1.0f, 0.5f, 1.0f/3.0f, 0.25f, 0.2f, 1.0f/6.0f,
                                1.0f/7.0f, 0.125f, 1.0f/9.0f, 0.1f, 1.0f/11.0f };

// ---------------- helpers ----------------
__device__ __forceinline__ uint32_t cvta_sh(const void* p) {
    uint32_t a;
    asm("{ .reg .u64 t; cvta.to.shared.u64 t, %1; cvt.u32.u64 %0, t; }" : "=r"(a) : "l"(p));
    return a;
}
__device__ __forceinline__ void cpasync16(uint32_t d, const void* s)
{
    asm volatile("cp.async.cg.shared.global [%0], [%1], 16;\n" :: "r"(d), "l"(s));
}
__device__ __forceinline__ void cp_commit() { asm volatile("cp.async.commit_group;\n" ::: "memory"); }
template<int N> __device__ __forceinline__ void cp_wait() { asm volatile("cp.async.wait_group %0;\n" :: "n"(N) : "memory"); }

__device__ __forceinline__ void ldm_x4(uint32_t addr, uint32_t* r)
{
    asm volatile("ldmatrix.sync.aligned.m8n8.x4.shared.b16 {%0,%1,%2,%3}, [%4];"
                 : "=r"(r[0]), "=r"(r[1]), "=r"(r[2]), "=r"(r[3]) : "r"(addr));
}
__device__ __forceinline__ void mma_f16(float* c, const uint32_t* a, uint32_t b0, uint32_t b1)
{
    asm volatile(
        "mma.sync.aligned.m16n8k16.row.col.f32.f16.f16.f32 "
        "{%0,%1,%2,%3},{%4,%5,%6,%7},{%8,%9},{%0,%1,%2,%3};\n"
        : "+f"(c[0]), "+f"(c[1]), "+f"(c[2]), "+f"(c[3])
        : "r"(a[0]), "r"(a[1]), "r"(a[2]), "r"(a[3]), "r"(b0), "r"(b1));
}
__device__ __forceinline__ uint32_t pack_h2(float lo, float hi)
{
    __half2 h = __floats2half2_rn(lo, hi);   // x=lo, y=hi
    return *(uint32_t*)&h;
}

// ---------------- k_w: W fp32 -> fp16 (MLP-4 unrolled) ----------------
__global__ void k_w(const float* __restrict__ W)
{
    const int base = blockIdx.x * 1024 + threadIdx.x;   // grid 32 x 256 thr x 4 float4
    #pragma unroll
    for (int i = 0; i < 4; i++) {
        const int u = base + i * 256;                   // float4 slot 0..32767
        float4 f = *(const float4*)(W + (size_t)u * 4);
        uint2 o;
        o.x = pack_h2(f.x, f.y);
        o.y = pack_h2(f.z, f.w);
        *(uint2*)(g_Wh + (size_t)u * 4) = o;
    }
}

// =====================================================================
// k_gemm (fp16) + folded prologue.
// Blocks 0..255:   g_Y[32768,128] = x @ W^T. 128x128 tile, 8 warps 4Mx2N
//                  (warp 32x64), BK=32; A: LDG fp32->cvt->STS.128 (2-stage);
//                  B: cp.async fp16 (3-stage); ONE barrier per chunk.
// Blocks 256..383: g_CsH[k][j*128+h] = fp16(cov[h][k]^j)
// Blocks 384..511: g_sigma'[j*128+h] = sum_k cov[h][k]^j
// =====================================================================
#define G1_ST   40                 // halves per smem row (32 + 8 pad)
#define G1_TILE (128*G1_ST*2)      // 10240 B per stage
#define G1_SMEM (5*G1_TILE)        // A x2 + B x3 = 51200 B

__global__ void __launch_bounds__(256, 2)
k_gemm(const float* __restrict__ A, const float* __restrict__ cov)
{
    const int tid = threadIdx.x;

    if (blockIdx.x >= 256) {                   // ---- folded prologue ----
        const int pb = blockIdx.x - 256;
        if (pb < 128) {
            if (tid < 128) {
                const int k = pb, h = tid;
                float c = cov[h*HD + k];
                float p = 1.0f;
                #pragma unroll
                for (int j = 0; j < NJ; j++) {
                    g_CsH[(size_t)k*K2 + j*HD + h] = __float2half(p);
                    p *= c;
                }
            }
        } else {
            const int h = pb - 128;
            __shared__ float part[4][NJ];
            if (tid < 128) {
                const int k = tid;
                float c = cov[h*HD + k];
                float p = 1.0f;
                #pragma unroll
                for (int j = 0; j < NJ; j++) {
                    float v = p;
                    #pragma unroll
                    for (int s = 16; s > 0; s >>= 1) v += __shfl_xor_sync(0xffffffffu, v, s);
                    if ((k & 31) == 0) part[k >> 5][j] = v;
                    p *= c;
                }
            }
            __syncthreads();
            if (tid < NJ)
                g_sigma[tid*HD + h] = part[0][tid] + part[1][tid] + part[2][tid] + part[3][tid];
        }
        return;
    }

    // ---- GEMM blocks ----
    extern __shared__ __align__(16) char smem[];
    const uint32_t AsA = cvta_sh(smem);               // 2 stages
    const uint32_t BsA = AsA + 2*G1_TILE;             // 3 stages

    const int lane = tid & 31, warp = tid >> 5;
    const int wm = warp & 3, wn = warp >> 2;
    const int mBase = blockIdx.x * 128;

    // A staging: 4 float4/thread/chunk as 2 runs of 8 floats; 1 STS.128 per run.
    const int ar2 = tid >> 2, aq8 = tid & 3;          // rows ar2 (+64), 8-float group aq8
    float4 a_st[4];

    auto ldA = [&](int c) {
        const int k0 = c * 32;
        #pragma unroll
        for (int i = 0; i < 2; i++) {
            const float* src = A + (size_t)(mBase + ar2 + i*64) * EMB + k0 + aq8*8;
            a_st[2*i]   = *(const float4*)(src);
            a_st[2*i+1] = *(const float4*)(src + 4);
        }
    };
    auto stA = [&](int c) {
        const uint32_t base = AsA + (uint32_t)((c & 1) * G1_TILE);
        #pragma unroll
        for (int i = 0; i < 2; i++) {
            uint4 o;
            o.x = pack_h2(a_st[2*i].x,   a_st[2*i].y);
            o.y = pack_h2(a_st[2*i].z,   a_st[2*i].w);
            o.z = pack_h2(a_st[2*i+1].x, a_st[2*i+1].y);
            o.w = pack_h2(a_st[2*i+1].z, a_st[2*i+1].w);
            asm volatile("st.shared.v4.b32 [%0], {%1, %2, %3, %4};" ::
                "r"(base + (uint32_t)(((ar2 + i*64)*G1_ST + aq8*8) * 2)),
                "r"(o.x), "r"(o.y), "r"(o.z), "r"(o.w));
        }
    };
    // B: 2 cp.async/thread/chunk (128 rows x 64B): slot s = tid + i*256: r = s>>2, q = s&3
    const int br = tid >> 2, bq_ = tid & 3;
    auto ldB = [&](int c) {
        const int k0 = c * 32, st = c % 3;
        #pragma unroll
        for (int i = 0; i < 2; i++)
            cpasync16(BsA + (uint32_t)(st*G1_TILE + ((br + i*64)*G1_ST + bq_*8)*2),
                      g_Wh + (size_t)(br + i*64) * EMB + k0 + bq_*8);
        cp_commit();
    };

    float acc[2][8][4] = {};

    const uint32_t rSel = lane & 15;
    const uint32_t hSel = (lane >> 4) * 8;            // halves
    const uint32_t aOff0 = ((wm*32 + rSel)*G1_ST + hSel) * 2;
    const uint32_t aOff1 = aOff0 + 16*G1_ST*2;
    uint32_t bOff[4];
    #pragma unroll
    for (int p = 0; p < 4; p++) bOff[p] = ((wn*64 + p*16 + rSel)*G1_ST + hSel) * 2;

    const int nCh = EMB / 32;   // 32
    ldA(0); stA(0); ldB(0);
    ldA(1); ldB(1);
    cp_wait<1>();
    __syncthreads();

    for (int c = 0; c < nCh; c++) {
        if (c + 2 < nCh) ldB(c + 2); else cp_commit();
        if (c + 1 < nCh) stA(c + 1);
        if (c + 2 < nCh) ldA(c + 2);

        const uint32_t aB = AsA + (uint32_t)((c & 1) * G1_TILE);
        const uint32_t bB = BsA + (uint32_t)((c % 3) * G1_TILE);
        #pragma unroll
        for (int ks = 0; ks < 2; ks++) {              // k16 steps
            uint32_t a0[4], a1[4], bq[4][4];
            ldm_x4(aB + aOff0 + ks*32, a0);
            ldm_x4(aB + aOff1 + ks*32, a1);
            #pragma unroll
            for (int p = 0; p < 4; p++) ldm_x4(bB + bOff[p] + ks*32, bq[p]);
            #pragma unroll
            for (int nt = 0; nt < 8; nt++) {
                const uint32_t b0 = bq[nt >> 1][nt & 1];
                const uint32_t b1 = bq[nt >> 1][2 + (nt & 1)];
                mma_f16(acc[0][nt], a0, b0, b1);
                mma_f16(acc[1][nt], a1, b0, b1);
            }
        }
        cp_wait<1>();
        __syncthreads();
    }

    // epilogue -> g_Y (fp32)
    const int g = lane >> 2, tg = lane & 3;
    #pragma unroll
    for (int mt = 0; mt < 2; mt++) {
        const size_t r0 = (size_t)(mBase + wm*32 + mt*16 + g);
        #pragma unroll
        for (int nt = 0; nt < 8; nt++) {
            const int c0 = wn*64 + nt*8 + tg*2;
            *(float2*)(g_Y + r0       * HD + c0) = make_float2(acc[mt][nt][0], acc[mt][nt][1]);
            *(float2*)(g_Y + (r0 + 8) * HD + c0) = make_float2(acc[mt][nt][2], acc[mt][nt][3]);
        }
    }
}

// =====================================================================
// k_out (fp16): fused (softmax-normalize + GEMM2), 64-row tiles, occ 2.
// cur_j = w * m^j / j!  (fp32 chain; fp16 mirror curH for ldmatrix)
// B_j   = c^j (fp16).  out = sum cur_j @ B_j^T + bias.
// 8 warps (2M x 4N), warp 32x32; 3-stage B cp.async (wait<1>); grid 256.
// sigma hoisted to registers (no smem staging). smem = 113664 B (occ 2).
// =====================================================================
#define KO_BST    40                  // halves per B smem row
#define KO_BTILE  (128*KO_BST*2)      // 10240 B
#define KO_BS_OFF   0                 // 3 stages = 30720
#define KO_M_OFF    30720             // fp32 [64][128] = 32768
#define KO_CUR_OFF  63488             // fp32 [64][128] = 32768
#define KO_CURH_OFF 96256             // fp16 [64][136] = 17408
#define KO_SMEM     113664

__global__ void __launch_bounds__(256, 2)
k_out(const float* __restrict__ bias, float* __restrict__ out)
{
    extern __shared__ __align__(16) char smc[];
    float*  m_s  = (float*)(smc + KO_M_OFF);
    float*  curS = (float*)(smc + KO_CUR_OFF);
    __half* curH = (__half*)(smc + KO_CURH_OFF);

    const int tid = threadIdx.x, lane = tid & 31, warp = tid >> 5;
    const int wm = warp & 1, wn = warp >> 1;          // 2M x 4N
    const int mBase = blockIdx.x * 64;
    const uint32_t BsA   = cvta_sh(smc + KO_BS_OFF);
    const uint32_t curHA = cvta_sh(curH);

    // B chunk: 128 rows x 32 halves (64B); 2 cp.async/thread; 3 stages
    auto loadB = [&](int c) {
        const int st = c % 3;
        #pragma unroll
        for (int i = 0; i < 2; i++) {
            const int s = tid + i*256, r = s >> 2, q = s & 3;
            cpasync16(BsA + (uint32_t)(st*KO_BTILE + (r*KO_BST + q*8)*2),
                      g_CsH + (size_t)r * K2 + c*32 + q*8);
        }
        cp_commit();
    };

    loadB(0); loadB(1);

    // sigma' for this thread's fixed h (= tid & 127) -> registers (L2-resident)
    const int myh = tid & 127;
    float sig[NJ];
    #pragma unroll
    for (int j = 0; j < NJ; j++) sig[j] = g_sigma[j*HD + myh];

    // init: m_s = m; curS = w = v / D; curH = fp16(w).  D = sum_j (m^j/j!) sigma'_j
    #pragma unroll 4
    for (int it = 0; it < 32; it++) {
        const int e = tid + it * 256;
        const int r = e >> 7;                 // h == myh for every iteration
        const float v = g_Y[(size_t)(2*(mBase + r)    ) * HD + myh];
        const float m = g_Y[(size_t)(2*(mBase + r) + 1) * HD + myh];
        float p = 1.0f, D = 0.0f;
        #pragma unroll
        for (int j = 0; j < NJ; j++) { D = fmaf(p, sig[j], D); p = p * m * c_rj[j+1]; }
        const float w = v / D;
        m_s [r*128 + myh] = m;
        curS[r*128 + myh] = w;
        curH[r*136 + myh] = __float2half(w);
    }
    cp_wait<1>();
    __syncthreads();

    float acc[2][4][4] = {};

    const uint32_t rSel = lane & 15;
    const uint32_t hSel = (lane >> 4) * 8;            // halves
    uint32_t aOff[2], bOff[2];
    #pragma unroll
    for (int t = 0; t < 2; t++) {
        aOff[t] = ((wm*32 + t*16 + rSel)*136 + hSel) * 2;   // curH stride 136 halves
        bOff[t] = ((wn*32 + t*16 + rSel)*KO_BST + hSel) * 2;
    }

    const int nCh = K2 / 32;   // 44 (4 chunks per j)
    for (int c = 0; c < nCh; c++) {
        if (c + 2 < nCh) loadB(c + 2); else cp_commit();

        const uint32_t aB = curHA + (uint32_t)((c & 3) * 64);   // +32 halves per h-block
        const uint32_t bB = BsA + (uint32_t)((c % 3) * KO_BTILE);
        #pragma unroll
        for (int ks = 0; ks < 2; ks++) {              // k16 steps
            uint32_t aq2[2][4], bq2[2][4];
            #pragma unroll
            for (int t = 0; t < 2; t++) {
                ldm_x4(aB + aOff[t] + ks*32, aq2[t]);
                ldm_x4(bB + bOff[t] + ks*32, bq2[t]);
            }
            #pragma unroll
            for (int mt = 0; mt < 2; mt++)
                #pragma unroll
                for (int nt = 0; nt < 4; nt++)
                    mma_f16(acc[mt][nt], aq2[mt],
                            bq2[nt >> 1][nt & 1], bq2[nt >> 1][2 + (nt & 1)]);
        }
        cp_wait<1>();
        __syncthreads();

        if ((c & 3) == 3 && c < nCh - 1) {            // j -> j+1: cur *= m/(j+1)
            const float sc = c_rj[(c >> 2) + 1];
            float4* cu = (float4*)curS;
            float4* mv = (float4*)m_s;
            #pragma unroll
            for (int it = 0; it < 8; it++) {
                const int e = tid + it * 256;         // 2048 data float4 slots
                const int r = e >> 5, s4 = e & 31;
                const int off = r*32 + s4;            // float4 stride 32 (=128 floats)
                float4 a = cu[off];
                const float4 b = mv[off];
                a.x *= b.x * sc; a.y *= b.y * sc; a.z *= b.z * sc; a.w *= b.w * sc;
                cu[off] = a;
                uint2 o;
                o.x = pack_h2(a.x, a.y);
                o.y = pack_h2(a.z, a.w);
                *(uint2*)(curH + r*136 + s4*4) = o;
            }
            __syncthreads();
        }
    }

    // epilogue: + bias -> out
    const int g = lane >> 2, tg = lane & 3;
    #pragma unroll
    for (int mt = 0; mt < 2; mt++) {
        const size_t r0 = (size_t)(mBase + wm*32 + mt*16 + g);
        #pragma unroll
        for (int nt = 0; nt < 4; nt++) {
            const int c0 = wn*32 + nt*8 + tg*2;
            const float b0 = bias[c0], b1 = bias[c0 + 1];
            *(float2*)(out + r0       * HD + c0) = make_float2(acc[mt][nt][0] + b0, acc[mt][nt][1] + b1);
            *(float2*)(out + (r0 + 8) * HD + c0) = make_float2(acc[mt][nt][2] + b0, acc[mt][nt][3] + b1);
        }
    }
}

// ---------------- launch ----------------
extern "C" void kernel_launch(void* const* d_in, const int* in_sizes, int n_in,
                              void* d_out, int out_size)
{
    const float* x    = (const float*)d_in[0];   // [16384,2,1024]
    const float* W    = (const float*)d_in[1];   // [128,1024]
    const float* cov  = (const float*)d_in[2];   // [128,128]
    const float* bias = (const float*)d_in[3];   // [128]
    float* out = (float*)d_out;                  // [16384,128]

    cudaFuncSetAttribute(k_gemm, cudaFuncAttributeMaxDynamicSharedMemorySize, G1_SMEM);
    cudaFuncSetAttribute(k_out,  cudaFuncAttributeMaxDynamicSharedMemorySize, KO_SMEM);

    k_w<<<32, 256>>>(W);                         // W -> fp16 (read by k_gemm next launch)
    k_gemm<<<512, 256, G1_SMEM>>>(x, cov);       // blocks 256..511: CsH + sigma'
    k_out<<<256, 256, KO_SMEM>>>(bias, out);
}

// round 15
// speedup vs baseline: 2.8569x; 1.0487x over previous
#include <cuda_runtime.h>
#include <cuda_fp16.h>
#include <cstdint>

// ---------------- problem sizes (fixed) ----------------
#define B_ROWS 16384
#define EMB    1024
#define HD     128
#define NJT    9               // Taylor terms j = 0..8 (truncated; error budget verified)
#define K2T    (NJT*HD)        // 1152

// ---------------- scratch (device globals; allocation-free) ----------------
__device__ float  g_Y[2*B_ROWS*HD];   // [32768,128] projections (even=values, odd=mask)
__device__ __half g_Wh[HD*EMB];       // W in fp16, [128][1024]
__device__ __half g_CsH[HD*K2T];      // [k_out(128)][j*128+h] = fp16(cov[h][k]^j)  (no 1/j!)
__device__ float  g_sigma[K2T];       // sigma'[j*128+h] = sum_k c^j  (no 1/j!)

__constant__ float c_rj[12] = { 0.0f, 1.0f, 0.5f, 1.0f/3.0f, 0.25f, 0.2f, 1.0f/6.0f,
                                1.0f/7.0f, 0.125f, 1.0f/9.0f, 0.1f, 1.0f/11.0f };

// ---------------- helpers ----------------
__device__ __forceinline__ uint32_t cvta_sh(const void* p) {
    uint32_t a;
    asm("{ .reg .u64 t; cvta.to.shared.u64 t, %1; cvt.u32.u64 %0, t; }" : "=r"(a) : "l"(p));
    return a;
}
__device__ __forceinline__ void cpasync16(uint32_t d, const void* s)
{
    asm volatile("cp.async.cg.shared.global [%0], [%1], 16;\n" :: "r"(d), "l"(s));
}
__device__ __forceinline__ void cp_commit() { asm volatile("cp.async.commit_group;\n" ::: "memory"); }
template<int N> __device__ __forceinline__ void cp_wait() { asm volatile("cp.async.wait_group %0;\n" :: "n"(N) : "memory"); }

__device__ __forceinline__ void ldm_x4(uint32_t addr, uint32_t* r)
{
    asm volatile("ldmatrix.sync.aligned.m8n8.x4.shared.b16 {%0,%1,%2,%3}, [%4];"
                 : "=r"(r[0]), "=r"(r[1]), "=r"(r[2]), "=r"(r[3]) : "r"(addr));
}
__device__ __forceinline__ void mma_f16(float* c, const uint32_t* a, uint32_t b0, uint32_t b1)
{
    asm volatile(
        "mma.sync.aligned.m16n8k16.row.col.f32.f16.f16.f32 "
        "{%0,%1,%2,%3},{%4,%5,%6,%7},{%8,%9},{%0,%1,%2,%3};\n"
        : "+f"(c[0]), "+f"(c[1]), "+f"(c[2]), "+f"(c[3])
        : "r"(a[0]), "r"(a[1]), "r"(a[2]), "r"(a[3]), "r"(b0), "r"(b1));
}
__device__ __forceinline__ uint32_t pack_h2(float lo, float hi)
{
    __half2 h = __floats2half2_rn(lo, hi);   // x=lo, y=hi
    return *(uint32_t*)&h;
}

// =====================================================================
// k_prep (one launch): W->fp16 (blocks 0..31, MLP-4), CsH (32..159),
// sigma' (160..287).
// =====================================================================
__global__ void k_prep(const float* __restrict__ W, const float* __restrict__ cov)
{
    const int bid = blockIdx.x, tid = threadIdx.x;
    if (bid < 32) {
        const int base = bid * 1024 + tid;            // float4 slots, 32x256x4 = 32768
        #pragma unroll
        for (int i = 0; i < 4; i++) {
            const int u = base + i * 256;
            float4 f = *(const float4*)(W + (size_t)u * 4);
            uint2 o;
            o.x = pack_h2(f.x, f.y);
            o.y = pack_h2(f.z, f.w);
            *(uint2*)(g_Wh + (size_t)u * 4) = o;
        }
    } else if (bid < 160) {
        if (tid < 128) {
            const int k = bid - 32, h = tid;
            float c = cov[h*HD + k];
            float p = 1.0f;
            #pragma unroll
            for (int j = 0; j < NJT; j++) {
                g_CsH[(size_t)k*K2T + j*HD + h] = __float2half(p);
                p *= c;
            }
        }
    } else {
        const int h = bid - 160;
        __shared__ float part[4][NJT];
        if (tid < 128) {
            const int k = tid;
            float c = cov[h*HD + k];
            float p = 1.0f;
            #pragma unroll
            for (int j = 0; j < NJT; j++) {
                float v = p;
                #pragma unroll
                for (int s = 16; s > 0; s >>= 1) v += __shfl_xor_sync(0xffffffffu, v, s);
                if ((k & 31) == 0) part[k >> 5][j] = v;
                p *= c;
            }
        }
        __syncthreads();
        if (tid < NJT)
            g_sigma[tid*HD + h] = part[0][tid] + part[1][tid] + part[2][tid] + part[3][tid];
    }
}

// =====================================================================
// k_gemm (fp16): g_Y[32768,128] = x @ W^T. 128x128 tile, 8 warps 4Mx2N
// (warp 32x64), BK=32; A: LDG fp32->cvt->STS.128 (2-stage);
// B: cp.async fp16 (3-stage); ONE barrier per chunk. Grid 256, occ 2.
// =====================================================================
#define G1_ST   40                 // halves per smem row (32 + 8 pad)
#define G1_TILE (128*G1_ST*2)      // 10240 B per stage
#define G1_SMEM (5*G1_TILE)        // A x2 + B x3 = 51200 B

__global__ void __launch_bounds__(256, 2)
k_gemm(const float* __restrict__ A)
{
    extern __shared__ __align__(16) char smem[];
    const uint32_t AsA = cvta_sh(smem);               // 2 stages
    const uint32_t BsA = AsA + 2*G1_TILE;             // 3 stages

    const int tid = threadIdx.x, lane = tid & 31, warp = tid >> 5;
    const int wm = warp & 3, wn = warp >> 2;
    const int mBase = blockIdx.x * 128;

    // A staging: 4 float4/thread/chunk as 2 runs of 8 floats; 1 STS.128 per run.
    const int ar2 = tid >> 2, aq8 = tid & 3;          // rows ar2 (+64), 8-float group aq8
    float4 a_st[4];

    auto ldA = [&](int c) {
        const int k0 = c * 32;
        #pragma unroll
        for (int i = 0; i < 2; i++) {
            const float* src = A + (size_t)(mBase + ar2 + i*64) * EMB + k0 + aq8*8;
            a_st[2*i]   = *(const float4*)(src);
            a_st[2*i+1] = *(const float4*)(src + 4);
        }
    };
    auto stA = [&](int c) {
        const uint32_t base = AsA + (uint32_t)((c & 1) * G1_TILE);
        #pragma unroll
        for (int i = 0; i < 2; i++) {
            uint4 o;
            o.x = pack_h2(a_st[2*i].x,   a_st[2*i].y);
            o.y = pack_h2(a_st[2*i].z,   a_st[2*i].w);
            o.z = pack_h2(a_st[2*i+1].x, a_st[2*i+1].y);
            o.w = pack_h2(a_st[2*i+1].z, a_st[2*i+1].w);
            asm volatile("st.shared.v4.b32 [%0], {%1, %2, %3, %4};" ::
                "r"(base + (uint32_t)(((ar2 + i*64)*G1_ST + aq8*8) * 2)),
                "r"(o.x), "r"(o.y), "r"(o.z), "r"(o.w));
        }
    };
    // B: 2 cp.async/thread/chunk (128 rows x 64B)
    const int br = tid >> 2, bq_ = tid & 3;
    auto ldB = [&](int c) {
        const int k0 = c * 32, st = c % 3;
        #pragma unroll
        for (int i = 0; i < 2; i++)
            cpasync16(BsA + (uint32_t)(st*G1_TILE + ((br + i*64)*G1_ST + bq_*8)*2),
                      g_Wh + (size_t)(br + i*64) * EMB + k0 + bq_*8);
        cp_commit();
    };

    float acc[2][8][4] = {};

    const uint32_t rSel = lane & 15;
    const uint32_t hSel = (lane >> 4) * 8;            // halves
    const uint32_t aOff0 = ((wm*32 + rSel)*G1_ST + hSel) * 2;
    const uint32_t aOff1 = aOff0 + 16*G1_ST*2;
    uint32_t bOff[4];
    #pragma unroll
    for (int p = 0; p < 4; p++) bOff[p] = ((wn*64 + p*16 + rSel)*G1_ST + hSel) * 2;

    const int nCh = EMB / 32;   // 32
    ldA(0); stA(0); ldB(0);
    ldA(1); ldB(1);
    cp_wait<1>();
    __syncthreads();

    for (int c = 0; c < nCh; c++) {
        if (c + 2 < nCh) ldB(c + 2); else cp_commit();
        if (c + 1 < nCh) stA(c + 1);
        if (c + 2 < nCh) ldA(c + 2);

        const uint32_t aB = AsA + (uint32_t)((c & 1) * G1_TILE);
        const uint32_t bB = BsA + (uint32_t)((c % 3) * G1_TILE);
        #pragma unroll
        for (int ks = 0; ks < 2; ks++) {              // k16 steps
            uint32_t a0[4], a1[4], bq[4][4];
            ldm_x4(aB + aOff0 + ks*32, a0);
            ldm_x4(aB + aOff1 + ks*32, a1);
            #pragma unroll
            for (int p = 0; p < 4; p++) ldm_x4(bB + bOff[p] + ks*32, bq[p]);
            #pragma unroll
            for (int nt = 0; nt < 8; nt++) {
                const uint32_t b0 = bq[nt >> 1][nt & 1];
                const uint32_t b1 = bq[nt >> 1][2 + (nt & 1)];
                mma_f16(acc[0][nt], a0, b0, b1);
                mma_f16(acc[1][nt], a1, b0, b1);
            }
        }
        cp_wait<1>();
        __syncthreads();
    }

    // epilogue -> g_Y (fp32)
    const int g = lane >> 2, tg = lane & 3;
    #pragma unroll
    for (int mt = 0; mt < 2; mt++) {
        const size_t r0 = (size_t)(mBase + wm*32 + mt*16 + g);
        #pragma unroll
        for (int nt = 0; nt < 8; nt++) {
            const int c0 = wn*64 + nt*8 + tg*2;
            *(float2*)(g_Y + r0       * HD + c0) = make_float2(acc[mt][nt][0], acc[mt][nt][1]);
            *(float2*)(g_Y + (r0 + 8) * HD + c0) = make_float2(acc[mt][nt][2], acc[mt][nt][3]);
        }
    }
}

// =====================================================================
// k_out (fp16): fused (softmax-normalize + GEMM2), 64-row tiles, occ 2.
// cur_j = w * m^j / j!  (fp32 chain; fp16 mirror curH for ldmatrix)
// B_j   = c^j (fp16).  out = sum_{j<NJT} cur_j @ B_j^T + bias.
// 8 warps (2M x 4N), warp 32x32; 3-stage B cp.async (wait<1>); grid 256.
// sigma hoisted to registers. smem = 113664 B (occ 2).
// =====================================================================
#define KO_BST    40                  // halves per B smem row
#define KO_BTILE  (128*KO_BST*2)      // 10240 B
#define KO_BS_OFF   0                 // 3 stages = 30720
#define KO_M_OFF    30720             // fp32 [64][128] = 32768
#define KO_CUR_OFF  63488             // fp32 [64][128] = 32768
#define KO_CURH_OFF 96256             // fp16 [64][136] = 17408
#define KO_SMEM     113664

__global__ void __launch_bounds__(256, 2)
k_out(const float* __restrict__ bias, float* __restrict__ out)
{
    extern __shared__ __align__(16) char smc[];
    float*  m_s  = (float*)(smc + KO_M_OFF);
    float*  curS = (float*)(smc + KO_CUR_OFF);
    __half* curH = (__half*)(smc + KO_CURH_OFF);

    const int tid = threadIdx.x, lane = tid & 31, warp = tid >> 5;
    const int wm = warp & 1, wn = warp >> 1;          // 2M x 4N
    const int mBase = blockIdx.x * 64;
    const uint32_t BsA   = cvta_sh(smc + KO_BS_OFF);
    const uint32_t curHA = cvta_sh(curH);

    // B chunk: 128 rows x 32 halves (64B); 2 cp.async/thread; 3 stages
    auto loadB = [&](int c) {
        const int st = c % 3;
        #pragma unroll
        for (int i = 0; i < 2; i++) {
            const int s = tid + i*256, r = s >> 2, q = s & 3;
            cpasync16(BsA + (uint32_t)(st*KO_BTILE + (r*KO_BST + q*8)*2),
                      g_CsH + (size_t)r * K2T + c*32 + q*8);
        }
        cp_commit();
    };

    loadB(0); loadB(1);

    // sigma' for this thread's fixed h (= tid & 127) -> registers (L2-resident)
    const int myh = tid & 127;
    float sig[NJT];
    #pragma unroll
    for (int j = 0; j < NJT; j++) sig[j] = g_sigma[j*HD + myh];

    // init: m_s = m; curS = w = v / D; curH = fp16(w).  D = sum_j (m^j/j!) sigma'_j
    #pragma unroll 4
    for (int it = 0; it < 32; it++) {
        const int e = tid + it * 256;
        const int r = e >> 7;                 // h == myh for every iteration
        const float v = g_Y[(size_t)(2*(mBase + r)    ) * HD + myh];
        const float m = g_Y[(size_t)(2*(mBase + r) + 1) * HD + myh];
        float p = 1.0f, D = 0.0f;
        #pragma unroll
        for (int j = 0; j < NJT; j++) { D = fmaf(p, sig[j], D); p = p * m * c_rj[j+1]; }
        const float w = v / D;
        m_s [r*128 + myh] = m;
        curS[r*128 + myh] = w;
        curH[r*136 + myh] = __float2half(w);
    }
    cp_wait<1>();
    __syncthreads();

    float acc[2][4][4] = {};

    const uint32_t rSel = lane & 15;
    const uint32_t hSel = (lane >> 4) * 8;            // halves
    uint32_t aOff[2], bOff[2];
    #pragma unroll
    for (int t = 0; t < 2; t++) {
        aOff[t] = ((wm*32 + t*16 + rSel)*136 + hSel) * 2;   // curH stride 136 halves
        bOff[t] = ((wn*32 + t*16 + rSel)*KO_BST + hSel) * 2;
    }

    const int nCh = K2T / 32;   // 36 (4 chunks per j)
    for (int c = 0; c < nCh; c++) {
        if (c + 2 < nCh) loadB(c + 2); else cp_commit();

        const uint32_t aB = curHA + (uint32_t)((c & 3) * 64);   // +32 halves per h-block
        const uint32_t bB = BsA + (uint32_t)((c % 3) * KO_BTILE);
        #pragma unroll
        for (int ks = 0; ks < 2; ks++) {              // k16 steps
            uint32_t aq2[2][4], bq2[2][4];
            #pragma unroll
            for (int t = 0; t < 2; t++) {
                ldm_x4(aB + aOff[t] + ks*32, aq2[t]);
                ldm_x4(bB + bOff[t] + ks*32, bq2[t]);
            }
            #pragma unroll
            for (int mt = 0; mt < 2; mt++)
                #pragma unroll
                for (int nt = 0; nt < 4; nt++)
                    mma_f16(acc[mt][nt], aq2[mt],
                            bq2[nt >> 1][nt & 1], bq2[nt >> 1][2 + (nt & 1)]);
        }
        cp_wait<1>();
        __syncthreads();

        if ((c & 3) == 3 && c < nCh - 1) {            // j -> j+1: cur *= m/(j+1)
            const float sc = c_rj[(c >> 2) + 1];
            float4* cu = (float4*)curS;
            float4* mv = (float4*)m_s;
            #pragma unroll
            for (int it = 0; it < 8; it++) {
                const int e = tid + it * 256;         // 2048 data float4 slots
                const int r = e >> 5, s4 = e & 31;
                const int off = r*32 + s4;            // float4 stride 32 (=128 floats)
                float4 a = cu[off];
                const float4 b = mv[off];
                a.x *= b.x * sc; a.y *= b.y * sc; a.z *= b.z * sc; a.w *= b.w * sc;
                cu[off] = a;
                uint2 o;
                o.x = pack_h2(a.x, a.y);
                o.y = pack_h2(a.z, a.w);
                *(uint2*)(curH + r*136 + s4*4) = o;
            }
            __syncthreads();
        }
    }

    // epilogue: + bias -> out
    const int g = lane >> 2, tg = lane & 3;
    #pragma unroll
    for (int mt = 0; mt < 2; mt++) {
        const size_t r0 = (size_t)(mBase + wm*32 + mt*16 + g);
        #pragma unroll
        for (int nt = 0; nt < 4; nt++) {
            const int c0 = wn*32 + nt*8 + tg*2;
            const float b0 = bias[c0], b1 = bias[c0 + 1];
            *(float2*)(out + r0       * HD + c0) = make_float2(acc[mt][nt][0] + b0, acc[mt][nt][1] + b1);
            *(float2*)(out + (r0 + 8) * HD + c0) = make_float2(acc[mt][nt][2] + b0, acc[mt][nt][3] + b1);
        }
    }
}

// ---------------- launch ----------------
extern "C" void kernel_launch(void* const* d_in, const int* in_sizes, int n_in,
                              void* d_out, int out_size)
{
    const float* x    = (const float*)d_in[0];   // [16384,2,1024]
    const float* W    = (const float*)d_in[1];   // [128,1024]
    const float* cov  = (const float*)d_in[2];   // [128,128]
    const float* bias = (const float*)d_in[3];   // [128]
    float* out = (float*)d_out;                  // [16384,128]

    cudaFuncSetAttribute(k_gemm, cudaFuncAttributeMaxDynamicSharedMemorySize, G1_SMEM);
    cudaFuncSetAttribute(k_out,  cudaFuncAttributeMaxDynamicSharedMemorySize, KO_SMEM);

    k_prep<<<288, 256>>>(W, cov);                // W->fp16, CsH, sigma'
    k_gemm<<<256, 256, G1_SMEM>>>(x);
    k_out<<<256, 256, KO_SMEM>>>(bias, out);
}

// round 16
// speedup vs baseline: 2.9146x; 1.0202x over previous
#include <cuda_runtime.h>
#include <cuda_fp16.h>
#include <cstdint>

// ---------------- problem sizes (fixed) ----------------
#define B_ROWS 16384
#define EMB    1024
#define HD     128
#define NJT    9               // Taylor terms j = 0..8
#define K2T    (NJT*HD)        // 1152

// ---------------- scratch (device globals; allocation-free) ----------------
__device__ __half g_Wh[HD*EMB];       // W in fp16, [128][1024]
__device__ __half g_CsH[HD*K2T];      // [k_out(128)][j*128+h] = fp16(cov[h][k]^j)
__device__ float  g_sigma[K2T];       // sigma'[j*128+h] = sum_k c^j

__constant__ float c_rj[12] = { 0.0f, 1.0f, 0.5f, 1.0f/3.0f, 0.25f, 0.2f, 1.0f/6.0f,
                                1.0f/7.0f, 0.125f, 1.0f/9.0f, 0.1f, 1.0f/11.0f };

// ---------------- helpers ----------------
__device__ __forceinline__ uint32_t cvta_sh(const void* p) {
    uint32_t a;
    asm("{ .reg .u64 t; cvta.to.shared.u64 t, %1; cvt.u32.u64 %0, t; }" : "=r"(a) : "l"(p));
    return a;
}
__device__ __forceinline__ void cpasync16(uint32_t d, const void* s)
{
    asm volatile("cp.async.cg.shared.global [%0], [%1], 16;\n" :: "r"(d), "l"(s));
}
__device__ __forceinline__ void cp_commit() { asm volatile("cp.async.commit_group;\n" ::: "memory"); }
template<int N> __device__ __forceinline__ void cp_wait() { asm volatile("cp.async.wait_group %0;\n" :: "n"(N) : "memory"); }

__device__ __forceinline__ void ldm_x4(uint32_t addr, uint32_t* r)
{
    asm volatile("ldmatrix.sync.aligned.m8n8.x4.shared.b16 {%0,%1,%2,%3}, [%4];"
                 : "=r"(r[0]), "=r"(r[1]), "=r"(r[2]), "=r"(r[3]) : "r"(addr));
}
__device__ __forceinline__ void mma_f16(float* c, const uint32_t* a, uint32_t b0, uint32_t b1)
{
    asm volatile(
        "mma.sync.aligned.m16n8k16.row.col.f32.f16.f16.f32 "
        "{%0,%1,%2,%3},{%4,%5,%6,%7},{%8,%9},{%0,%1,%2,%3};\n"
        : "+f"(c[0]), "+f"(c[1]), "+f"(c[2]), "+f"(c[3])
        : "r"(a[0]), "r"(a[1]), "r"(a[2]), "r"(a[3]), "r"(b0), "r"(b1));
}
__device__ __forceinline__ uint32_t pack_h2(float lo, float hi)
{
    __half2 h = __floats2half2_rn(lo, hi);   // x=lo, y=hi
    return *(uint32_t*)&h;
}

// =====================================================================
// k_prep (one launch): W->fp16 (blocks 0..31, MLP-4), CsH (32..159),
// sigma' (160..287).
// =====================================================================
__global__ void k_prep(const float* __restrict__ W, const float* __restrict__ cov)
{
    const int bid = blockIdx.x, tid = threadIdx.x;
    if (bid < 32) {
        const int base = bid * 1024 + tid;
        #pragma unroll
        for (int i = 0; i < 4; i++) {
            const int u = base + i * 256;
            float4 f = *(const float4*)(W + (size_t)u * 4);
            uint2 o;
            o.x = pack_h2(f.x, f.y);
            o.y = pack_h2(f.z, f.w);
            *(uint2*)(g_Wh + (size_t)u * 4) = o;
        }
    } else if (bid < 160) {
        if (tid < 128) {
            const int k = bid - 32, h = tid;
            float c = cov[h*HD + k];
            float p = 1.0f;
            #pragma unroll
            for (int j = 0; j < NJT; j++) {
                g_CsH[(size_t)k*K2T + j*HD + h] = __float2half(p);
                p *= c;
            }
        }
    } else {
        const int h = bid - 160;
        __shared__ float part[4][NJT];
        if (tid < 128) {
            const int k = tid;
            float c = cov[h*HD + k];
            float p = 1.0f;
            #pragma unroll
            for (int j = 0; j < NJT; j++) {
                float v = p;
                #pragma unroll
                for (int s = 16; s > 0; s >>= 1) v += __shfl_xor_sync(0xffffffffu, v, s);
                if ((k & 31) == 0) part[k >> 5][j] = v;
                p *= c;
            }
        }
        __syncthreads();
        if (tid < NJT)
            g_sigma[tid*HD + h] = part[0][tid] + part[1][tid] + part[2][tid] + part[3][tid];
    }
}

// =====================================================================
// k_main: FULLY FUSED. One CTA owns 64 b-rows (128 Y-rows).
// Phase 1: Y = x @ W^T (fp16 HMMA, 128x128 tile, 8 warps 4Mx2N) -> smem.
// Normalize: w = v / D (sigma' in regs), curH = fp16(w).
// Phase 2: out = sum_j cur_j @ Cs_j^T + bias (8 warps 2Mx4N),
//          cur_{j+1} = cur_j * m/(j+1) in fp32, fp16 mirror.
// smem union: phase-2 B stages overlay dead phase-1 stages. occ 2.
// =====================================================================
#define G1_ST   40                 // halves per smem row (32 + 8 pad)
#define G1_TILE (128*G1_ST*2)      // 10240 B per stage
// phase 1: As = [0, 20480), Bs = [20480, 51200)
// phase 2: B2 = [0, 30720), m_s = [30720, 63488), curS = [63488, 96256),
//          curH = [96256, 113664)
#define FU_B2_OFF   0
#define FU_M_OFF    30720
#define FU_CUR_OFF  63488
#define FU_CURH_OFF 96256
#define FU_SMEM     113664

__global__ void __launch_bounds__(256, 2)
k_main(const float* __restrict__ A, const float* __restrict__ bias,
       float* __restrict__ out)
{
    extern __shared__ __align__(16) char smc[];
    float*  m_s  = (float*)(smc + FU_M_OFF);     // [64][128] fp32
    float*  curS = (float*)(smc + FU_CUR_OFF);   // [64][128] fp32
    __half* curH = (__half*)(smc + FU_CURH_OFF); // [64][136] fp16

    const int tid = threadIdx.x, lane = tid & 31, warp = tid >> 5;
    const int mBase = blockIdx.x * 128;          // Y-row base (= 2 * b-row base)
    const uint32_t smB  = cvta_sh(smc);
    const uint32_t AsA  = smB;                   // phase 1: 2 stages
    const uint32_t BsA  = smB + 2*G1_TILE;       // phase 1: 3 stages
    const uint32_t B2A  = smB + FU_B2_OFF;       // phase 2: 3 stages
    const uint32_t curHA = cvta_sh(curH);

    // ================= PHASE 1: GEMM1 =================
    {
        const int wm = warp & 3, wn = warp >> 2;

        const int ar2 = tid >> 2, aq8 = tid & 3;
        float4 a_st[4];

        auto ldA = [&](int c) {
            const int k0 = c * 32;
            #pragma unroll
            for (int i = 0; i < 2; i++) {
                const float* src = A + (size_t)(mBase + ar2 + i*64) * EMB + k0 + aq8*8;
                a_st[2*i]   = *(const float4*)(src);
                a_st[2*i+1] = *(const float4*)(src + 4);
            }
        };
        auto stA = [&](int c) {
            const uint32_t base = AsA + (uint32_t)((c & 1) * G1_TILE);
            #pragma unroll
            for (int i = 0; i < 2; i++) {
                uint4 o;
                o.x = pack_h2(a_st[2*i].x,   a_st[2*i].y);
                o.y = pack_h2(a_st[2*i].z,   a_st[2*i].w);
                o.z = pack_h2(a_st[2*i+1].x, a_st[2*i+1].y);
                o.w = pack_h2(a_st[2*i+1].z, a_st[2*i+1].w);
                asm volatile("st.shared.v4.b32 [%0], {%1, %2, %3, %4};" ::
                    "r"(base + (uint32_t)(((ar2 + i*64)*G1_ST + aq8*8) * 2)),
                    "r"(o.x), "r"(o.y), "r"(o.z), "r"(o.w));
            }
        };
        const int br = tid >> 2, bq_ = tid & 3;
        auto ldB = [&](int c) {
            const int k0 = c * 32, st = c % 3;
            #pragma unroll
            for (int i = 0; i < 2; i++)
                cpasync16(BsA + (uint32_t)(st*G1_TILE + ((br + i*64)*G1_ST + bq_*8)*2),
                          g_Wh + (size_t)(br + i*64) * EMB + k0 + bq_*8);
            cp_commit();
        };

        float acc[2][8][4] = {};

        const uint32_t rSel = lane & 15;
        const uint32_t hSel = (lane >> 4) * 8;
        const uint32_t aOff0 = ((wm*32 + rSel)*G1_ST + hSel) * 2;
        const uint32_t aOff1 = aOff0 + 16*G1_ST*2;
        uint32_t bOff[4];
        #pragma unroll
        for (int p = 0; p < 4; p++) bOff[p] = ((wn*64 + p*16 + rSel)*G1_ST + hSel) * 2;

        const int nCh = EMB / 32;   // 32
        ldA(0); stA(0); ldB(0);
        ldA(1); ldB(1);
        cp_wait<1>();
        __syncthreads();

        for (int c = 0; c < nCh; c++) {
            if (c + 2 < nCh) ldB(c + 2); else cp_commit();
            if (c + 1 < nCh) stA(c + 1);
            if (c + 2 < nCh) ldA(c + 2);

            const uint32_t aB = AsA + (uint32_t)((c & 1) * G1_TILE);
            const uint32_t bB = BsA + (uint32_t)((c % 3) * G1_TILE);
            #pragma unroll
            for (int ks = 0; ks < 2; ks++) {
                uint32_t a0[4], a1[4], bq[4][4];
                ldm_x4(aB + aOff0 + ks*32, a0);
                ldm_x4(aB + aOff1 + ks*32, a1);
                #pragma unroll
                for (int p = 0; p < 4; p++) ldm_x4(bB + bOff[p] + ks*32, bq[p]);
                #pragma unroll
                for (int nt = 0; nt < 8; nt++) {
                    const uint32_t b0 = bq[nt >> 1][nt & 1];
                    const uint32_t b1 = bq[nt >> 1][2 + (nt & 1)];
                    mma_f16(acc[0][nt], a0, b0, b1);
                    mma_f16(acc[1][nt], a1, b0, b1);
                }
            }
            cp_wait<1>();
            __syncthreads();
        }

        // phase-2 B prefetch overlaps the epilogue/normalize (writes [0,30720))
        {
            #pragma unroll
            for (int cc = 0; cc < 2; cc++) {
                #pragma unroll
                for (int i = 0; i < 2; i++) {
                    const int s = tid + i*256, r = s >> 2, q = s & 3;
                    cpasync16(B2A + (uint32_t)((cc % 3)*G1_TILE + (r*G1_ST + q*8)*2),
                              g_CsH + (size_t)r * K2T + cc*32 + q*8);
                }
                cp_commit();
            }
        }

        // epilogue -> smem (even Y-row = v -> curS, odd = m -> m_s)
        const int g = lane >> 2, tg = lane & 3;
        #pragma unroll
        for (int mt = 0; mt < 2; mt++) {
            const int r0 = wm*32 + mt*16 + g;            // tile-local Y row (parity = g&1)
            float* dst = (r0 & 1) ? m_s : curS;
            const int b0r = r0 >> 1;                     // b-row 0..63
            #pragma unroll
            for (int nt = 0; nt < 8; nt++) {
                const int c0 = wn*64 + nt*8 + tg*2;
                *(float2*)(dst + (b0r    )*128 + c0) = make_float2(acc[mt][nt][0], acc[mt][nt][1]);
                *(float2*)(dst + (b0r + 4)*128 + c0) = make_float2(acc[mt][nt][2], acc[mt][nt][3]);
            }
        }
    }
    __syncthreads();

    // ================= NORMALIZE =================
    {
        const int myh = tid & 127;
        float sig[NJT];
        #pragma unroll
        for (int j = 0; j < NJT; j++) sig[j] = g_sigma[j*HD + myh];

        #pragma unroll 4
        for (int it = 0; it < 32; it++) {
            const int r = (tid + it * 256) >> 7;        // 0..63
            const float v = curS[r*128 + myh];
            const float m = m_s [r*128 + myh];
            float p = 1.0f, D = 0.0f;
            #pragma unroll
            for (int j = 0; j < NJT; j++) { D = fmaf(p, sig[j], D); p = p * m * c_rj[j+1]; }
            const float w = v / D;
            curS[r*128 + myh] = w;
            curH[r*136 + myh] = __float2half(w);
        }
    }
    cp_wait<1>();
    __syncthreads();

    // ================= PHASE 2: GEMM2 =================
    {
        const int wm = warp & 1, wn = warp >> 1;        // 2M x 4N

        auto loadB2 = [&](int c) {
            const int st = c % 3;
            #pragma unroll
            for (int i = 0; i < 2; i++) {
                const int s = tid + i*256, r = s >> 2, q = s & 3;
                cpasync16(B2A + (uint32_t)(st*G1_TILE + (r*G1_ST + q*8)*2),
                          g_CsH + (size_t)r * K2T + c*32 + q*8);
            }
            cp_commit();
        };

        float acc[2][4][4] = {};

        const uint32_t rSel = lane & 15;
        const uint32_t hSel = (lane >> 4) * 8;
        uint32_t aOff[2], bOff[2];
        #pragma unroll
        for (int t = 0; t < 2; t++) {
            aOff[t] = ((wm*32 + t*16 + rSel)*136 + hSel) * 2;   // curH stride 136 halves
            bOff[t] = ((wn*32 + t*16 + rSel)*G1_ST + hSel) * 2;
        }

        const int nCh = K2T / 32;   // 36
        for (int c = 0; c < nCh; c++) {
            if (c + 2 < nCh) loadB2(c + 2); else cp_commit();

            const uint32_t aB = curHA + (uint32_t)((c & 3) * 64);
            const uint32_t bB = B2A + (uint32_t)((c % 3) * G1_TILE);
            #pragma unroll
            for (int ks = 0; ks < 2; ks++) {
                uint32_t aq2[2][4], bq2[2][4];
                #pragma unroll
                for (int t = 0; t < 2; t++) {
                    ldm_x4(aB + aOff[t] + ks*32, aq2[t]);
                    ldm_x4(bB + bOff[t] + ks*32, bq2[t]);
                }
                #pragma unroll
                for (int mt = 0; mt < 2; mt++)
                    #pragma unroll
                    for (int nt = 0; nt < 4; nt++)
                        mma_f16(acc[mt][nt], aq2[mt],
                                bq2[nt >> 1][nt & 1], bq2[nt >> 1][2 + (nt & 1)]);
            }
            cp_wait<1>();
            __syncthreads();

            if ((c & 3) == 3 && c < nCh - 1) {          // j -> j+1: cur *= m/(j+1)
                const float sc = c_rj[(c >> 2) + 1];
                float4* cu = (float4*)curS;
                float4* mv = (float4*)m_s;
                #pragma unroll
                for (int it = 0; it < 8; it++) {
                    const int e = tid + it * 256;       // 2048 data float4 slots
                    const int r = e >> 5, s4 = e & 31;
                    const int off = r*32 + s4;
                    float4 a = cu[off];
                    const float4 b = mv[off];
                    a.x *= b.x * sc; a.y *= b.y * sc; a.z *= b.z * sc; a.w *= b.w * sc;
                    cu[off] = a;
                    uint2 o;
                    o.x = pack_h2(a.x, a.y);
                    o.y = pack_h2(a.z, a.w);
                    *(uint2*)(curH + r*136 + s4*4) = o;
                }
                __syncthreads();
            }
        }

        // epilogue: + bias -> out (b-rows mBase/2 .. mBase/2+63)
        const int g = lane >> 2, tg = lane & 3;
        const int bBase = mBase >> 1;
        #pragma unroll
        for (int mt = 0; mt < 2; mt++) {
            const size_t r0 = (size_t)(bBase + wm*32 + mt*16 + g);
            #pragma unroll
            for (int nt = 0; nt < 4; nt++) {
                const int c0 = wn*32 + nt*8 + tg*2;
                const float b0 = bias[c0], b1 = bias[c0 + 1];
                *(float2*)(out + r0       * HD + c0) = make_float2(acc[mt][nt][0] + b0, acc[mt][nt][1] + b1);
                *(float2*)(out + (r0 + 8) * HD + c0) = make_float2(acc[mt][nt][2] + b0, acc[mt][nt][3] + b1);
            }
        }
    }
}

// ---------------- launch ----------------
extern "C" void kernel_launch(void* const* d_in, const int* in_sizes, int n_in,
                              void* d_out, int out_size)
{
    const float* x    = (const float*)d_in[0];   // [16384,2,1024]
    const float* W    = (const float*)d_in[1];   // [128,1024]
    const float* cov  = (const float*)d_in[2];   // [128,128]
    const float* bias = (const float*)d_in[3];   // [128]
    float* out = (float*)d_out;                  // [16384,128]

    cudaFuncSetAttribute(k_main, cudaFuncAttributeMaxDynamicSharedMemorySize, FU_SMEM);

    k_prep<<<288, 256>>>(W, cov);                // W->fp16, CsH, sigma'
    k_main<<<256, 256, FU_SMEM>>>(x, bias, out);
}

// round 17
// speedup vs baseline: 3.2197x; 1.1047x over previous
#include <cuda_runtime.h>
#include <cuda_fp16.h>
#include <cstdint>

// ---------------- problem sizes (fixed) ----------------
#define B_ROWS 16384
#define EMB    1024
#define HD     128
#define NJT    9               // Taylor terms j = 0..8
#define K2T    (NJT*HD)        // 1152

// ---------------- scratch (device globals; allocation-free) ----------------
__device__ __half g_Wh[HD*EMB];       // W in fp16, [128][1024]
__device__ __half g_CsH[HD*K2T];      // [k_out(128)][j*128+h] = fp16(cov[h][k]^j)
__device__ float  g_sigma[K2T];       // sigma'[j*128+h] = sum_k c^j

__constant__ float c_rj[12] = { 0.0f, 1.0f, 0.5f, 1.0f/3.0f, 0.25f, 0.2f, 1.0f/6.0f,
                                1.0f/7.0f, 0.125f, 1.0f/9.0f, 0.1f, 1.0f/11.0f };

// ---------------- helpers ----------------
__device__ __forceinline__ uint32_t cvta_sh(const void* p) {
    uint32_t a;
    asm("{ .reg .u64 t; cvta.to.shared.u64 t, %1; cvt.u32.u64 %0, t; }" : "=r"(a) : "l"(p));
    return a;
}
__device__ __forceinline__ void cpasync16(uint32_t d, const void* s)
{
    asm volatile("cp.async.cg.shared.global [%0], [%1], 16;\n" :: "r"(d), "l"(s));
}
__device__ __forceinline__ void cp_commit() { asm volatile("cp.async.commit_group;\n" ::: "memory"); }
template<int N> __device__ __forceinline__ void cp_wait() { asm volatile("cp.async.wait_group %0;\n" :: "n"(N) : "memory"); }

__device__ __forceinline__ void ldm_x4(uint32_t addr, uint32_t* r)
{
    asm volatile("ldmatrix.sync.aligned.m8n8.x4.shared.b16 {%0,%1,%2,%3}, [%4];"
                 : "=r"(r[0]), "=r"(r[1]), "=r"(r[2]), "=r"(r[3]) : "r"(addr));
}
__device__ __forceinline__ void mma_f16(float* c, const uint32_t* a, uint32_t b0, uint32_t b1)
{
    asm volatile(
        "mma.sync.aligned.m16n8k16.row.col.f32.f16.f16.f32 "
        "{%0,%1,%2,%3},{%4,%5,%6,%7},{%8,%9},{%0,%1,%2,%3};\n"
        : "+f"(c[0]), "+f"(c[1]), "+f"(c[2]), "+f"(c[3])
        : "r"(a[0]), "r"(a[1]), "r"(a[2]), "r"(a[3]), "r"(b0), "r"(b1));
}
__device__ __forceinline__ uint32_t pack_h2(float lo, float hi)
{
    __half2 h = __floats2half2_rn(lo, hi);
    return *(uint32_t*)&h;
}

// =====================================================================
// k_prep (one launch): W->fp16 (blocks 0..31, MLP-4), CsH (32..159),
// sigma' (160..287).
// =====================================================================
__global__ void k_prep(const float* __restrict__ W, const float* __restrict__ cov)
{
    const int bid = blockIdx.x, tid = threadIdx.x;
    if (bid < 32) {
        const int base = bid * 1024 + tid;
        #pragma unroll
        for (int i = 0; i < 4; i++) {
            const int u = base + i * 256;
            float4 f = *(const float4*)(W + (size_t)u * 4);
            uint2 o;
            o.x = pack_h2(f.x, f.y);
            o.y = pack_h2(f.z, f.w);
            *(uint2*)(g_Wh + (size_t)u * 4) = o;
        }
    } else if (bid < 160) {
        if (tid < 128) {
            const int k = bid - 32, h = tid;
            float c = cov[h*HD + k];
            float p = 1.0f;
            #pragma unroll
            for (int j = 0; j < NJT; j++) {
                g_CsH[(size_t)k*K2T + j*HD + h] = __float2half(p);
                p *= c;
            }
        }
    } else {
        const int h = bid - 160;
        __shared__ float part[4][NJT];
        if (tid < 128) {
            const int k = tid;
            float c = cov[h*HD + k];
            float p = 1.0f;
            #pragma unroll
            for (int j = 0; j < NJT; j++) {
                float v = p;
                #pragma unroll
                for (int s = 16; s > 0; s >>= 1) v += __shfl_xor_sync(0xffffffffu, v, s);
                if ((k & 31) == 0) part[k >> 5][j] = v;
                p *= c;
            }
        }
        __syncthreads();
        if (tid < NJT)
            g_sigma[tid*HD + h] = part[0][tid] + part[1][tid] + part[2][tid] + part[3][tid];
    }
}

// =====================================================================
// k_main: FULLY FUSED, phase-1 BK=64 (16 chunks, 1 barrier each).
// Phase 1: Y = x @ W^T (fp16 HMMA, 128x128 tile, 8 warps 4Mx2N) -> smem.
//          A: LDG fp32->cvt->STS.128, staged in HALF-chunks interleaved
//          with the two ks-pairs (16 staging regs). B: cp.async, 3-stage.
// Normalize: w = v / D (sigma' in regs), curH = fp16(w).
// Phase 2: out = sum_j cur_j @ Cs_j^T + bias (8 warps 2Mx4N, BK=32).
// smem union 113664 B, occ 2.
// =====================================================================
#define P1_ST   72                 // halves per phase-1 smem row (64 + 8 pad)
#define P1_TILE (128*P1_ST*2)      // 18432 B per stage
// phase 1: As 2 stages [0, 36864), Bs 3 stages [36864, 92160)
#define P2_ST   40                 // halves per phase-2 B row (32 + 8 pad)
#define P2_TILE (128*P2_ST*2)      // 10240 B
#define FU_B2_OFF   0              // 3 stages = 30720
#define FU_M_OFF    30720          // fp32 [64][128] = 32768
#define FU_CUR_OFF  63488          // fp32 [64][128] = 32768
#define FU_CURH_OFF 96256          // fp16 [64][136] = 17408
#define FU_SMEM     113664

__global__ void __launch_bounds__(256, 2)
k_main(const float* __restrict__ A, const float* __restrict__ bias,
       float* __restrict__ out)
{
    extern __shared__ __align__(16) char smc[];
    float*  m_s  = (float*)(smc + FU_M_OFF);
    float*  curS = (float*)(smc + FU_CUR_OFF);
    __half* curH = (__half*)(smc + FU_CURH_OFF);

    const int tid = threadIdx.x, lane = tid & 31, warp = tid >> 5;
    const int mBase = blockIdx.x * 128;
    const uint32_t smB   = cvta_sh(smc);
    const uint32_t AsA   = smB;                  // 2 stages x 18432
    const uint32_t BsA   = smB + 2*P1_TILE;      // 3 stages x 18432
    const uint32_t B2A   = smB + FU_B2_OFF;      // phase 2: 3 stages x 10240
    const uint32_t curHA = cvta_sh(curH);

    // ================= PHASE 1: GEMM1 (BK = 64) =================
    {
        const int wm = warp & 3, wn = warp >> 2;

        // A half-chunk staging: 4 float4/thread. Thread covers 2 rows
        // (ar2, ar2+64) x 16 floats at col aq8*16 within the 32-float half.
        const int ar2 = tid >> 2, aq8 = tid & 3;
        float4 a_st[4];

        auto ldA = [&](int c, int half) {            // half-chunk (32 K)
            const int k0 = c * 64 + half * 32;
            #pragma unroll
            for (int i = 0; i < 2; i++) {
                const float* src = A + (size_t)(mBase + ar2 + i*64) * EMB + k0 + aq8*8;
                a_st[2*i]   = *(const float4*)(src);
                a_st[2*i+1] = *(const float4*)(src + 4);
            }
        };
        auto stA = [&](int c, int half) {
            const uint32_t base = AsA + (uint32_t)((c & 1) * P1_TILE)
                                + (uint32_t)(half * 32 * 2);
            #pragma unroll
            for (int i = 0; i < 2; i++) {
                uint4 o;
                o.x = pack_h2(a_st[2*i].x,   a_st[2*i].y);
                o.y = pack_h2(a_st[2*i].z,   a_st[2*i].w);
                o.z = pack_h2(a_st[2*i+1].x, a_st[2*i+1].y);
                o.w = pack_h2(a_st[2*i+1].z, a_st[2*i+1].w);
                asm volatile("st.shared.v4.b32 [%0], {%1, %2, %3, %4};" ::
                    "r"(base + (uint32_t)(((ar2 + i*64)*P1_ST + aq8*8) * 2)),
                    "r"(o.x), "r"(o.y), "r"(o.z), "r"(o.w));
            }
        };
        // B chunk: 128 rows x 64 halves (128 B/row); 4 cp.async/thread
        auto ldB = [&](int c) {
            const int k0 = c * 64, st = c % 3;
            #pragma unroll
            for (int i = 0; i < 4; i++) {
                const int s = tid + i*256, r = s >> 3, q = s & 7;
                cpasync16(BsA + (uint32_t)(st*P1_TILE + (r*P1_ST + q*8)*2),
                          g_Wh + (size_t)r * EMB + k0 + q*8);
            }
            cp_commit();
        };

        float acc[2][8][4] = {};

        const uint32_t rSel = lane & 15;
        const uint32_t hSel = (lane >> 4) * 8;
        const uint32_t aOff0 = ((wm*32 + rSel)*P1_ST + hSel) * 2;
        const uint32_t aOff1 = aOff0 + 16*P1_ST*2;
        uint32_t bOff[4];
        #pragma unroll
        for (int p = 0; p < 4; p++) bOff[p] = ((wn*64 + p*16 + rSel)*P1_ST + hSel) * 2;

        auto mma_pair = [&](uint32_t aB, uint32_t bB, int ks) {
            uint32_t a0[4], a1[4], bq[4][4];
            ldm_x4(aB + aOff0 + ks*32, a0);
            ldm_x4(aB + aOff1 + ks*32, a1);
            #pragma unroll
            for (int p = 0; p < 4; p++) ldm_x4(bB + bOff[p] + ks*32, bq[p]);
            #pragma unroll
            for (int nt = 0; nt < 8; nt++) {
                const uint32_t b0 = bq[nt >> 1][nt & 1];
                const uint32_t b1 = bq[nt >> 1][2 + (nt & 1)];
                mma_f16(acc[0][nt], a0, b0, b1);
                mma_f16(acc[1][nt], a1, b0, b1);
            }
        };

        const int nCh = EMB / 64;   // 16
        // prologue: chunk 0 fully staged; B 0,1 in flight; chunk1 half0 in regs
        ldA(0, 0); stA(0, 0);
        ldA(0, 1); stA(0, 1);
        ldB(0); ldB(1);
        ldA(1, 0);
        cp_wait<1>();
        __syncthreads();

        for (int c = 0; c < nCh; c++) {
            if (c + 2 < nCh) ldB(c + 2); else cp_commit();

            const uint32_t aB = AsA + (uint32_t)((c & 1) * P1_TILE);
            const uint32_t bB = BsA + (uint32_t)((c % 3) * P1_TILE);

            if (c + 1 < nCh) stA(c + 1, 0);     // flush (c+1, h0) held in regs
            if (c + 1 < nCh) ldA(c + 1, 1);     // fetch (c+1, h1)

            mma_pair(aB, bB, 0);
            mma_pair(aB, bB, 1);

            if (c + 1 < nCh) stA(c + 1, 1);     // flush (c+1, h1)
            if (c + 2 < nCh) ldA(c + 2, 0);     // fetch (c+2, h0)

            mma_pair(aB, bB, 2);
            mma_pair(aB, bB, 3);

            cp_wait<1>();
            __syncthreads();
        }

        // phase-2 B prefetch (chunks 0,1) — A/B stages are dead past the barrier
        #pragma unroll
        for (int cc = 0; cc < 2; cc++) {
            #pragma unroll
            for (int i = 0; i < 2; i++) {
                const int s = tid + i*256, r = s >> 2, q = s & 3;
                cpasync16(B2A + (uint32_t)((cc % 3)*P2_TILE + (r*P2_ST + q*8)*2),
                          g_CsH + (size_t)r * K2T + cc*32 + q*8);
            }
            cp_commit();
        }

        // epilogue -> smem (even Y-row = v -> curS, odd = m -> m_s)
        const int g = lane >> 2, tg = lane & 3;
        #pragma unroll
        for (int mt = 0; mt < 2; mt++) {
            const int r0 = wm*32 + mt*16 + g;
            float* dst = (r0 & 1) ? m_s : curS;
            const int b0r = r0 >> 1;
            #pragma unroll
            for (int nt = 0; nt < 8; nt++) {
                const int c0 = wn*64 + nt*8 + tg*2;
                *(float2*)(dst + (b0r    )*128 + c0) = make_float2(acc[mt][nt][0], acc[mt][nt][1]);
                *(float2*)(dst + (b0r + 4)*128 + c0) = make_float2(acc[mt][nt][2], acc[mt][nt][3]);
            }
        }
    }
    __syncthreads();

    // ================= NORMALIZE =================
    {
        const int myh = tid & 127;
        float sig[NJT];
        #pragma unroll
        for (int j = 0; j < NJT; j++) sig[j] = g_sigma[j*HD + myh];

        #pragma unroll 4
        for (int it = 0; it < 32; it++) {
            const int r = (tid + it * 256) >> 7;
            const float v = curS[r*128 + myh];
            const float m = m_s [r*128 + myh];
            float p = 1.0f, D = 0.0f;
            #pragma unroll
            for (int j = 0; j < NJT; j++) { D = fmaf(p, sig[j], D); p = p * m * c_rj[j+1]; }
            const float w = v / D;
            curS[r*128 + myh] = w;
            curH[r*136 + myh] = __float2half(w);
        }
    }
    cp_wait<1>();
    __syncthreads();

    // ================= PHASE 2: GEMM2 (BK = 32) =================
    {
        const int wm = warp & 1, wn = warp >> 1;

        auto loadB2 = [&](int c) {
            const int st = c % 3;
            #pragma unroll
            for (int i = 0; i < 2; i++) {
                const int s = tid + i*256, r = s >> 2, q = s & 3;
                cpasync16(B2A + (uint32_t)(st*P2_TILE + (r*P2_ST + q*8)*2),
                          g_CsH + (size_t)r * K2T + c*32 + q*8);
            }
            cp_commit();
        };

        float acc[2][4][4] = {};

        const uint32_t rSel = lane & 15;
        const uint32_t hSel = (lane >> 4) * 8;
        uint32_t aOff[2], bOff[2];
        #pragma unroll
        for (int t = 0; t < 2; t++) {
            aOff[t] = ((wm*32 + t*16 + rSel)*136 + hSel) * 2;
            bOff[t] = ((wn*32 + t*16 + rSel)*P2_ST + hSel) * 2;
        }

        const int nCh = K2T / 32;   // 36
        for (int c = 0; c < nCh; c++) {
            if (c + 2 < nCh) loadB2(c + 2); else cp_commit();

            const uint32_t aB = curHA + (uint32_t)((c & 3) * 64);
            const uint32_t bB = B2A + (uint32_t)((c % 3) * P2_TILE);
            #pragma unroll
            for (int ks = 0; ks < 2; ks++) {
                uint32_t aq2[2][4], bq2[2][4];
                #pragma unroll
                for (int t = 0; t < 2; t++) {
                    ldm_x4(aB + aOff[t] + ks*32, aq2[t]);
                    ldm_x4(bB + bOff[t] + ks*32, bq2[t]);
                }
                #pragma unroll
                for (int mt = 0; mt < 2; mt++)
                    #pragma unroll
                    for (int nt = 0; nt < 4; nt++)
                        mma_f16(acc[mt][nt], aq2[mt],
                                bq2[nt >> 1][nt & 1], bq2[nt >> 1][2 + (nt & 1)]);
            }
            cp_wait<1>();
            __syncthreads();

            if ((c & 3) == 3 && c < nCh - 1) {          // j -> j+1: cur *= m/(j+1)
                const float sc = c_rj[(c >> 2) + 1];
                float4* cu = (float4*)curS;
                float4* mv = (float4*)m_s;
                #pragma unroll
                for (int it = 0; it < 8; it++) {
                    const int e = tid + it * 256;
                    const int r = e >> 5, s4 = e & 31;
                    const int off = r*32 + s4;
                    float4 a = cu[off];
                    const float4 b = mv[off];
                    a.x *= b.x * sc; a.y *= b.y * sc; a.z *= b.z * sc; a.w *= b.w * sc;
                    cu[off] = a;
                    uint2 o;
                    o.x = pack_h2(a.x, a.y);
                    o.y = pack_h2(a.z, a.w);
                    *(uint2*)(curH + r*136 + s4*4) = o;
                }
                __syncthreads();
            }
        }

        // epilogue: + bias -> out
        const int g = lane >> 2, tg = lane & 3;
        const int bBase = mBase >> 1;
        #pragma unroll
        for (int mt = 0; mt < 2; mt++) {
            const size_t r0 = (size_t)(bBase + wm*32 + mt*16 + g);
            #pragma unroll
            for (int nt = 0; nt < 4; nt++) {
                const int c0 = wn*32 + nt*8 + tg*2;
                const float b0 = bias[c0], b1 = bias[c0 + 1];
                *(float2*)(out + r0       * HD + c0) = make_float2(acc[mt][nt][0] + b0, acc[mt][nt][1] + b1);
                *(float2*)(out + (r0 + 8) * HD + c0) = make_float2(acc[mt][nt][2] + b0, acc[mt][nt][3] + b1);
            }
        }
    }
}

// ---------------- launch ----------------
extern "C" void kernel_launch(void* const* d_in, const int* in_sizes, int n_in,
                              void* d_out, int out_size)
{
    const float* x    = (const float*)d_in[0];   // [16384,2,1024]
    const float* W    = (const float*)d_in[1];   // [128,1024]
    const float* cov  = (const float*)d_in[2];   // [128,128]
    const float* bias = (const float*)d_in[3];   // [128]
    float* out = (float*)d_out;                  // [16384,128]

    cudaFuncSetAttribute(k_main, cudaFuncAttributeMaxDynamicSharedMemorySize, FU_SMEM);

    k_prep<<<288, 256>>>(W, cov);                // W->fp16, CsH, sigma'
    k_main<<<256, 256, FU_SMEM>>>(x, bias, out);
}